// round 8
// baseline (speedup 1.0000x reference)
#include <cuda_runtime.h>
#include <math.h>
#include <stdint.h>

// ---------------- problem constants ----------------
#define SEQ   1024
#define HID   2048
#define NH    16
#define KVH   4
#define HD    128
#define FDIM  7168
#define NEXP  8
#define PADROWS 3072
#define MTILES  24
#define EPSV  1e-5f
#define SCALE 0.08838834764831845f

// ---------------- device scratch ----------------
__device__ float g_xn  [SEQ*HID];
__device__ float g_q   [SEQ*NH*HD];
__device__ float g_k   [SEQ*KVH*HD];
__device__ float g_v   [SEQ*KVH*HD];
__device__ float g_P   [(size_t)NH*SEQ*SEQ];
__device__ float g_attn[SEQ*HID];
__device__ float g_x1  [SEQ*HID];
__device__ float g_xn2 [SEQ*HID];
__device__ float g_Hup [(size_t)PADROWS*FDIM];
__device__ float g_Dout[(size_t)PADROWS*HID];
__device__ float g_topw[SEQ*2];
__device__ int   g_topi[SEQ*2];
__device__ int   g_assign[PADROWS];
__device__ int   g_tilee[MTILES];
__device__ int   g_slot[SEQ*2];

__device__ __forceinline__ float f2tf_f(float f) {
    uint32_t u;
    asm("cvt.rna.tf32.f32 %0, %1;" : "=r"(u) : "f"(f));
    return __uint_as_float(u);
}

__device__ __forceinline__ void mma_tf32(float* c, uint32_t a0, uint32_t a1,
                                         uint32_t a2, uint32_t a3,
                                         uint32_t b0, uint32_t b1)
{
    asm volatile(
        "mma.sync.aligned.m16n8k8.row.col.f32.tf32.tf32.f32 "
        "{%0,%1,%2,%3}, {%4,%5,%6,%7}, {%8,%9}, {%0,%1,%2,%3};"
        : "+f"(c[0]), "+f"(c[1]), "+f"(c[2]), "+f"(c[3])
        : "r"(a0), "r"(a1), "r"(a2), "r"(a3), "r"(b0), "r"(b1));
}

// Packed-A smem: float offset for A[row][k] within one buffer.
// Layout: [k8 0..3][rp 0..7][grp 0..7] -> uint4 group of 4 q-slots, XOR-swizzled.
// Fragment load: one LDS.128 gives {A[r][k8*8+q], A[r][k8*8+q+4], A[r+8][..q], A[r+8][..q+4]}
#define A_BUF_FLOATS 4096   // 4*8*8*4 uint4 = 1024 uint4

__device__ __forceinline__ int a_pack_off(int row, int k) {
    int k8 = k >> 3, q = k & 3, u = (k >> 2) & 1;
    int rp = row >> 4, grp = row & 7, rhal = (row >> 3) & 1;
    return (((k8 * 8 + rp) * 8 + grp) << 4) + ((q ^ (grp & 3) ^ k8) << 2) + rhal * 2 + u;
}

// ================= main GEMM: block 128x256, 512 thr, warp 64x32 (2x8) =================
#define BPAD256 264
#define TCG_SMEM ((2*A_BUF_FLOATS + 2*32*BPAD256) * 4)

__global__ __launch_bounds__(512, 1)
void tc_gemm(const float* __restrict__ A, int lda,
             const float* __restrict__ B, int ldb,
             const float* __restrict__ Dadd,
             float* __restrict__ C, int ldc, int K,
             const int* __restrict__ tilee,
             long long bstride)
{
    extern __shared__ float smem_f[];
    float* sA = smem_f;                         // 2 x A_BUF_FLOATS
    float* sB = smem_f + 2 * A_BUF_FLOATS;      // 2 x 32 x BPAD256

    const int m0 = blockIdx.y * 128, n0 = blockIdx.x * 256;
    if (tilee) {
        int e = tilee[blockIdx.y];
        if (e < 0) return;
        B += (size_t)e * bstride;
    }

    const int tid  = threadIdx.x;
    const int lane = tid & 31, wid = tid >> 5;
    const int wm = wid & 1, wn = wid >> 1;       // 2x8 warp grid: 64-row x 32-col tiles
    const int grp = lane >> 2, qid = lane & 3;

    float acc[4][4][4] = {};
    float4 sa[2], sb[4];
    const int nk = K >> 5;

    int a_row[2], a_c4[2], a_off[2][4];
#pragma unroll
    for (int i = 0; i < 2; i++) {
        int idx = i * 512 + tid;
        a_row[i] = idx >> 3;
        a_c4[i]  = (idx & 7) << 2;
#pragma unroll
        for (int q = 0; q < 4; q++)
            a_off[i][q] = a_pack_off(a_row[i], a_c4[i] + q);
    }
    const int b_row = tid >> 6, b_c4 = (tid & 63) << 2;

    auto load_stage = [&](int kt) {
        const int k0 = kt << 5;
#pragma unroll
        for (int i = 0; i < 2; i++)
            sa[i] = *(const float4*)(A + (size_t)(m0 + a_row[i]) * lda + k0 + a_c4[i]);
#pragma unroll
        for (int i = 0; i < 4; i++)
            sb[i] = *(const float4*)(B + (size_t)(k0 + b_row + i * 8) * ldb + n0 + b_c4);
    };
    auto store_stage = [&](int buf) {
        float* Ab = sA + buf * A_BUF_FLOATS;
        float* Bb = sB + buf * 32 * BPAD256;
#pragma unroll
        for (int i = 0; i < 2; i++) {
            Ab[a_off[i][0]] = f2tf_f(sa[i].x); Ab[a_off[i][1]] = f2tf_f(sa[i].y);
            Ab[a_off[i][2]] = f2tf_f(sa[i].z); Ab[a_off[i][3]] = f2tf_f(sa[i].w);
        }
#pragma unroll
        for (int i = 0; i < 4; i++) {
            float4 v = sb[i];
            v.x = f2tf_f(v.x); v.y = f2tf_f(v.y);
            v.z = f2tf_f(v.z); v.w = f2tf_f(v.w);
            *(float4*)(Bb + (b_row + i * 8) * BPAD256 + b_c4) = v;
        }
    };

    load_stage(0);
    store_stage(0);
    __syncthreads();

    for (int kt = 0; kt < nk; kt++) {
        if (kt + 1 < nk) load_stage(kt + 1);

        const float* Ab = sA + (kt & 1) * A_BUF_FLOATS;
        const float* Bb = sB + (kt & 1) * 32 * BPAD256;
#pragma unroll
        for (int k8 = 0; k8 < 4; k8++) {
            uint32_t bf[4][2];
#pragma unroll
            for (int j = 0; j < 4; j++) {
                int colb = wn * 32 + j * 8 + grp;
                bf[j][0] = __float_as_uint(Bb[(k8 * 8 + qid) * BPAD256 + colb]);
                bf[j][1] = __float_as_uint(Bb[(k8 * 8 + qid + 4) * BPAD256 + colb]);
            }
#pragma unroll
            for (int i = 0; i < 4; i++) {
                int rp = wm * 4 + i;
                const uint4 av = *(const uint4*)(Ab +
                    (((k8 * 8 + rp) * 8 + grp) << 4) + ((qid ^ (grp & 3) ^ k8) << 2));
#pragma unroll
                for (int j = 0; j < 4; j++)
                    mma_tf32(acc[i][j], av.x, av.z, av.y, av.w, bf[j][0], bf[j][1]);
            }
        }

        if (kt + 1 < nk) store_stage((kt + 1) & 1);
        __syncthreads();
    }

#pragma unroll
    for (int i = 0; i < 4; i++) {
#pragma unroll
        for (int j = 0; j < 4; j++) {
            int r0 = m0 + wm * 64 + i * 16 + grp;
            int r1 = r0 + 8;
            int c  = n0 + wn * 32 + j * 8 + qid * 2;
            float2 v0 = { acc[i][j][0], acc[i][j][1] };
            float2 v1 = { acc[i][j][2], acc[i][j][3] };
            if (Dadd) {
                float2 d0 = *(const float2*)(Dadd + (size_t)r0 * ldc + c);
                float2 d1 = *(const float2*)(Dadd + (size_t)r1 * ldc + c);
                v0.x += d0.x; v0.y += d0.y;
                v1.x += d1.x; v1.y += d1.y;
            }
            *(float2*)(C + (size_t)r0 * ldc + c) = v0;
            *(float2*)(C + (size_t)r1 * ldc + c) = v1;
        }
    }
}

// ============ fused upgate: block 128x128, 512 thr, warp 32x32 (4x4), dual B ============
#define BPAD128 136
#define UPG_SMEM ((2*A_BUF_FLOATS + 4*32*BPAD128 + 128) * 4)

__global__ __launch_bounds__(512, 1)
void tc_gemm_upgate(const float* __restrict__ A, int lda,
                    const float* __restrict__ B1, const float* __restrict__ B2,
                    float* __restrict__ C,
                    const int* __restrict__ ridx,
                    const int* __restrict__ tilee,
                    long long bstride)
{
    extern __shared__ float smem_f[];
    float* sA  = smem_f;                          // 2 x A_BUF_FLOATS
    float* sB1 = smem_f + 2 * A_BUF_FLOATS;       // 2 x 32 x BPAD128
    float* sB2 = sB1 + 2 * 32 * BPAD128;          // 2 x 32 x BPAD128
    int* ridx_sm = (int*)(sB2 + 2 * 32 * BPAD128);

    const int m0 = blockIdx.y * 128, n0 = blockIdx.x * 128;
    int e = tilee[blockIdx.y];
    if (e < 0) return;
    B1 += (size_t)e * bstride;
    B2 += (size_t)e * bstride;

    const int tid  = threadIdx.x;
    const int lane = tid & 31, wid = tid >> 5;
    const int wm = wid & 3, wn = wid >> 2;        // 4x4
    const int grp = lane >> 2, qid = lane & 3;

    if (tid < 128) ridx_sm[tid] = ridx[m0 + tid];
    __syncthreads();

    float acc1[2][4][4] = {}, acc2[2][4][4] = {};
    float4 sa[2], sb1[2], sb2[2];
    const int nk = HID >> 5;

    int a_row[2], a_c4[2], a_off[2][4];
#pragma unroll
    for (int i = 0; i < 2; i++) {
        int idx = i * 512 + tid;
        a_row[i] = idx >> 3;
        a_c4[i]  = (idx & 7) << 2;
#pragma unroll
        for (int q = 0; q < 4; q++)
            a_off[i][q] = a_pack_off(a_row[i], a_c4[i] + q);
    }
    const int b_row = tid >> 5, b_c4 = (tid & 31) << 2;

    auto load_stage = [&](int kt) {
        const int k0 = kt << 5;
#pragma unroll
        for (int i = 0; i < 2; i++) {
            int r = ridx_sm[a_row[i]];
            sa[i] = (r >= 0) ? *(const float4*)(A + (size_t)r * lda + k0 + a_c4[i])
                             : make_float4(0.f, 0.f, 0.f, 0.f);
        }
#pragma unroll
        for (int i = 0; i < 2; i++) {
            sb1[i] = *(const float4*)(B1 + (size_t)(k0 + b_row + i * 16) * FDIM + n0 + b_c4);
            sb2[i] = *(const float4*)(B2 + (size_t)(k0 + b_row + i * 16) * FDIM + n0 + b_c4);
        }
    };
    auto store_stage = [&](int buf) {
        float* Ab  = sA + buf * A_BUF_FLOATS;
        float* B1b = sB1 + buf * 32 * BPAD128;
        float* B2b = sB2 + buf * 32 * BPAD128;
#pragma unroll
        for (int i = 0; i < 2; i++) {
            Ab[a_off[i][0]] = f2tf_f(sa[i].x); Ab[a_off[i][1]] = f2tf_f(sa[i].y);
            Ab[a_off[i][2]] = f2tf_f(sa[i].z); Ab[a_off[i][3]] = f2tf_f(sa[i].w);
        }
#pragma unroll
        for (int i = 0; i < 2; i++) {
            float4 v1 = sb1[i], v2 = sb2[i];
            v1.x = f2tf_f(v1.x); v1.y = f2tf_f(v1.y); v1.z = f2tf_f(v1.z); v1.w = f2tf_f(v1.w);
            v2.x = f2tf_f(v2.x); v2.y = f2tf_f(v2.y); v2.z = f2tf_f(v2.z); v2.w = f2tf_f(v2.w);
            *(float4*)(B1b + (b_row + i * 16) * BPAD128 + b_c4) = v1;
            *(float4*)(B2b + (b_row + i * 16) * BPAD128 + b_c4) = v2;
        }
    };

    load_stage(0);
    store_stage(0);
    __syncthreads();

    for (int kt = 0; kt < nk; kt++) {
        if (kt + 1 < nk) load_stage(kt + 1);

        const float* Ab  = sA + (kt & 1) * A_BUF_FLOATS;
        const float* B1b = sB1 + (kt & 1) * 32 * BPAD128;
        const float* B2b = sB2 + (kt & 1) * 32 * BPAD128;
#pragma unroll
        for (int k8 = 0; k8 < 4; k8++) {
            uint32_t bf1[4][2], bf2[4][2];
#pragma unroll
            for (int j = 0; j < 4; j++) {
                int colb = wn * 32 + j * 8 + grp;
                bf1[j][0] = __float_as_uint(B1b[(k8 * 8 + qid) * BPAD128 + colb]);
                bf1[j][1] = __float_as_uint(B1b[(k8 * 8 + qid + 4) * BPAD128 + colb]);
                bf2[j][0] = __float_as_uint(B2b[(k8 * 8 + qid) * BPAD128 + colb]);
                bf2[j][1] = __float_as_uint(B2b[(k8 * 8 + qid + 4) * BPAD128 + colb]);
            }
#pragma unroll
            for (int i = 0; i < 2; i++) {
                int rp = wm * 2 + i;
                const uint4 av = *(const uint4*)(Ab +
                    (((k8 * 8 + rp) * 8 + grp) << 4) + ((qid ^ (grp & 3) ^ k8) << 2));
#pragma unroll
                for (int j = 0; j < 4; j++) {
                    mma_tf32(acc1[i][j], av.x, av.z, av.y, av.w, bf1[j][0], bf1[j][1]);
                    mma_tf32(acc2[i][j], av.x, av.z, av.y, av.w, bf2[j][0], bf2[j][1]);
                }
            }
        }

        if (kt + 1 < nk) store_stage((kt + 1) & 1);
        __syncthreads();
    }

#pragma unroll
    for (int i = 0; i < 2; i++) {
#pragma unroll
        for (int j = 0; j < 4; j++) {
            int r0 = m0 + wm * 32 + i * 16 + grp;
            int r1 = r0 + 8;
            int c  = n0 + wn * 32 + j * 8 + qid * 2;
            float u, g;
            float2 v0, v1;
            u = acc1[i][j][0]; g = acc2[i][j][0]; v0.x = (u / (1.f + expf(-u))) * g;
            u = acc1[i][j][1]; g = acc2[i][j][1]; v0.y = (u / (1.f + expf(-u))) * g;
            u = acc1[i][j][2]; g = acc2[i][j][2]; v1.x = (u / (1.f + expf(-u))) * g;
            u = acc1[i][j][3]; g = acc2[i][j][3]; v1.y = (u / (1.f + expf(-u))) * g;
            *(float2*)(C + (size_t)r0 * FDIM + c) = v0;
            *(float2*)(C + (size_t)r1 * FDIM + c) = v1;
        }
    }
}

// ---------------- RMSNorm ----------------
__global__ void rmsnorm_kernel(const float* __restrict__ x, const float* __restrict__ w,
                               float* __restrict__ y)
{
    int t = blockIdx.x;
    const float* xr = x + (size_t)t * HID;
    float ss = 0.f;
    for (int j = threadIdx.x; j < HID; j += 256) { float v = xr[j]; ss += v * v; }
    __shared__ float sm[256];
    sm[threadIdx.x] = ss; __syncthreads();
    for (int o = 128; o > 0; o >>= 1) {
        if (threadIdx.x < o) sm[threadIdx.x] += sm[threadIdx.x + o];
        __syncthreads();
    }
    float inv = rsqrtf(sm[0] / (float)HID + EPSV);
    for (int j = threadIdx.x; j < HID; j += 256)
        y[(size_t)t * HID + j] = w[j] * (xr[j] * inv);
}

// ---------------- RoPE ----------------
__global__ void rope_kernel(const float* __restrict__ cosb, const float* __restrict__ sinb)
{
    int t = blockIdx.x, hh = blockIdx.y, d = threadIdx.x;
    float* p = (hh < NH) ? (g_q + (size_t)t * NH * HD + hh * HD)
                         : (g_k + (size_t)t * KVH * HD + (hh - NH) * HD);
    __shared__ float buf[HD];
    float x = p[d];
    buf[d] = x;
    __syncthreads();
    float rot = (d < HD / 2) ? -buf[d + HD / 2] : buf[d - HD / 2];
    p[d] = x * cosb[t * HD + d] + rot * sinb[t * HD + d];
}

// ---------------- scores ----------------
__global__ __launch_bounds__(256)
void attn_scores_kernel()
{
    const int h = blockIdx.z;
    const int m0 = blockIdx.y * 64, n0 = blockIdx.x * 64;
    if (n0 > m0 + 63) return;
    const float* A  = g_q + h * HD;
    const float* Bm = g_k + (h >> 2) * HD;
    float* C = g_P + (size_t)h * SEQ * SEQ;
    __shared__ float As[16][65];
    __shared__ float Bs[16][65];
    const int tid = threadIdx.x;
    const int tx = tid & 15, ty = tid >> 4;
    const int a_m = tid >> 2, a_k = (tid & 3) << 2;
    float acc[4][4] = {};
    for (int k0 = 0; k0 < HD; k0 += 16) {
        float4 av = *(const float4*)(A + (size_t)(m0 + a_m) * (NH * HD) + k0 + a_k);
        As[a_k + 0][a_m] = av.x; As[a_k + 1][a_m] = av.y;
        As[a_k + 2][a_m] = av.z; As[a_k + 3][a_m] = av.w;
        float4 bv = *(const float4*)(Bm + (size_t)(n0 + a_m) * (KVH * HD) + k0 + a_k);
        Bs[a_k + 0][a_m] = bv.x; Bs[a_k + 1][a_m] = bv.y;
        Bs[a_k + 2][a_m] = bv.z; Bs[a_k + 3][a_m] = bv.w;
        __syncthreads();
#pragma unroll
        for (int kk = 0; kk < 16; kk++) {
            float a[4], b[4];
#pragma unroll
            for (int i = 0; i < 4; i++) a[i] = As[kk][ty * 4 + i];
#pragma unroll
            for (int j = 0; j < 4; j++) b[j] = Bs[kk][tx * 4 + j];
#pragma unroll
            for (int i = 0; i < 4; i++)
#pragma unroll
                for (int j = 0; j < 4; j++)
                    acc[i][j] = fmaf(a[i], b[j], acc[i][j]);
        }
        __syncthreads();
    }
#pragma unroll
    for (int i = 0; i < 4; i++) {
        size_t off = (size_t)(m0 + ty * 4 + i) * SEQ + n0 + tx * 4;
        float4 r = { acc[i][0] * SCALE, acc[i][1] * SCALE, acc[i][2] * SCALE, acc[i][3] * SCALE };
        *(float4*)(C + off) = r;
    }
}

// ---------------- softmax ----------------
__global__ void softmax_kernel()
{
    int t = blockIdx.x, h = blockIdx.y, tid = threadIdx.x;
    float* row = g_P + ((size_t)h * SEQ + t) * SEQ;
    int n = t + 1;
    __shared__ float sm[256];
    float mx = -1e30f;
    for (int j = tid; j < n; j += 256) mx = fmaxf(mx, row[j]);
    sm[tid] = mx; __syncthreads();
    for (int o = 128; o > 0; o >>= 1) {
        if (tid < o) sm[tid] = fmaxf(sm[tid], sm[tid + o]);
        __syncthreads();
    }
    float m = sm[0];
    __syncthreads();
    float sum = 0.f;
    for (int j = tid; j < n; j += 256) {
        float e = expf(row[j] - m);
        row[j] = e;
        sum += e;
    }
    sm[tid] = sum; __syncthreads();
    for (int o = 128; o > 0; o >>= 1) {
        if (tid < o) sm[tid] += sm[tid + o];
        __syncthreads();
    }
    float inv = 1.f / sm[0];
    for (int j = tid; j < SEQ; j += 256)
        row[j] = (j < n) ? row[j] * inv : 0.f;
}

// ---------------- attn = P @ V ----------------
__global__ __launch_bounds__(256)
void attn_pv_kernel()
{
    const int h = blockIdx.z;
    const int m0 = blockIdx.y * 64, n0 = blockIdx.x * 64;
    const float* A = g_P + (size_t)h * SEQ * SEQ;
    const float* B = g_v + (h >> 2) * HD;
    float* C = g_attn + h * HD;
    const int kend = m0 + 64;
    __shared__ float As[16][65];
    __shared__ float Bs[16][64];
    const int tid = threadIdx.x;
    const int tx = tid & 15, ty = tid >> 4;
    const int a_m = tid >> 2, a_k = (tid & 3) << 2;
    const int b_k = tid >> 4, b_n = (tid & 15) << 2;
    float acc[4][4] = {};
    for (int k0 = 0; k0 < kend; k0 += 16) {
        float4 av = *(const float4*)(A + (size_t)(m0 + a_m) * SEQ + k0 + a_k);
        As[a_k + 0][a_m] = av.x; As[a_k + 1][a_m] = av.y;
        As[a_k + 2][a_m] = av.z; As[a_k + 3][a_m] = av.w;
        *(float4*)&Bs[b_k][b_n] = *(const float4*)(B + (size_t)(k0 + b_k) * (KVH * HD) + n0 + b_n);
        __syncthreads();
#pragma unroll
        for (int kk = 0; kk < 16; kk++) {
            float a[4];
#pragma unroll
            for (int i = 0; i < 4; i++) a[i] = As[kk][ty * 4 + i];
            float4 bv = *(const float4*)&Bs[kk][tx * 4];
            float b[4] = { bv.x, bv.y, bv.z, bv.w };
#pragma unroll
            for (int i = 0; i < 4; i++)
#pragma unroll
                for (int j = 0; j < 4; j++)
                    acc[i][j] = fmaf(a[i], b[j], acc[i][j]);
        }
        __syncthreads();
    }
#pragma unroll
    for (int i = 0; i < 4; i++) {
        size_t off = (size_t)(m0 + ty * 4 + i) * HID + n0 + tx * 4;
        float4 r = { acc[i][0], acc[i][1], acc[i][2], acc[i][3] };
        *(float4*)(C + off) = r;
    }
}

// ---------------- routing ----------------
__global__ void route_kernel(const float* __restrict__ gw)
{
    int t = blockIdx.x, tid = threadIdx.x;
    float acc[8] = {};
    for (int hh = tid; hh < HID; hh += 256) {
        float xv = g_xn2[(size_t)t * HID + hh];
        const float* gr = gw + hh * 8;
        float4 a0 = *(const float4*)gr, a1 = *(const float4*)(gr + 4);
        acc[0] += xv * a0.x; acc[1] += xv * a0.y; acc[2] += xv * a0.z; acc[3] += xv * a0.w;
        acc[4] += xv * a1.x; acc[5] += xv * a1.y; acc[6] += xv * a1.z; acc[7] += xv * a1.w;
    }
#pragma unroll
    for (int o = 16; o > 0; o >>= 1)
#pragma unroll
        for (int e = 0; e < 8; e++)
            acc[e] += __shfl_down_sync(0xffffffffu, acc[e], o);
    __shared__ float sm[8][8];
    int w = tid >> 5, lane = tid & 31;
    if (lane == 0)
#pragma unroll
        for (int e = 0; e < 8; e++) sm[w][e] = acc[e];
    __syncthreads();
    if (tid == 0) {
        float l[8];
        for (int e = 0; e < 8; e++) {
            float s = 0.f;
            for (int ww = 0; ww < 8; ww++) s += sm[ww][e];
            l[e] = s;
        }
        int i0 = 0;
        for (int e = 1; e < 8; e++) if (l[e] > l[i0]) i0 = e;
        int i1 = -1;
        for (int e = 0; e < 8; e++) if (e != i0 && (i1 < 0 || l[e] > l[i1])) i1 = e;
        float p0 = 1.f, p1 = expf(l[i1] - l[i0]);
        float s = p0 + p1;
        g_topi[t * 2] = i0; g_topi[t * 2 + 1] = i1;
        g_topw[t * 2] = p0 / s; g_topw[t * 2 + 1] = p1 / s;
    }
}

// ---------------- grouping ----------------
__global__ void group_kernel()
{
    int tid = threadIdx.x;
    for (int i = tid; i < PADROWS; i += 256) g_assign[i] = -1;
    if (tid < MTILES) g_tilee[tid] = -1;
    __shared__ int cnt[NEXP], off[NEXP];
    if (tid < NEXP) cnt[tid] = 0;
    __syncthreads();
    for (int a = tid; a < SEQ * 2; a += 256) atomicAdd(&cnt[g_topi[a]], 1);
    __syncthreads();
    if (tid == 0) {
        int cur = 0;
        for (int e = 0; e < NEXP; e++) {
            off[e] = cur;
            int tiles = (cnt[e] + 127) >> 7;
            for (int tt = 0; tt < tiles; tt++) g_tilee[(cur >> 7) + tt] = e;
            cur += tiles * 128;
        }
    }
    __syncthreads();
    int w = tid >> 5, lane = tid & 31;
    if (w < NEXP) {
        int e = w, base = off[e], filled = 0;
        for (int a0 = 0; a0 < SEQ * 2; a0 += 32) {
            int a = a0 + lane;
            int ti = g_topi[a];
            bool match = (ti == e);
            unsigned msk = __ballot_sync(0xffffffffu, match);
            if (match) {
                int rank = __popc(msk & ((1u << lane) - 1u));
                int slot = base + filled + rank;
                g_assign[slot] = a >> 1;
                g_slot[a] = slot;
            }
            filled += __popc(msk);
        }
    }
}

// ---------------- combine ----------------
__global__ void combine_kernel(float* __restrict__ out)
{
    int t = blockIdx.x;
    int s0 = g_slot[t * 2], s1 = g_slot[t * 2 + 1];
    float w0 = g_topw[t * 2], w1 = g_topw[t * 2 + 1];
    for (int j = threadIdx.x; j < HID; j += 256) {
        size_t o = (size_t)t * HID + j;
        out[o] = g_x1[o] + w0 * g_Dout[(size_t)s0 * HID + j]
                         + w1 * g_Dout[(size_t)s1 * HID + j];
    }
}

// ---------------- launch ----------------
extern "C" void kernel_launch(void* const* d_in, const int* in_sizes, int n_in,
                              void* d_out, int out_size)
{
    const float* hidden = (const float*)d_in[0];
    const float* cosb   = (const float*)d_in[1];
    const float* sinb   = (const float*)d_in[2];
    const float* q_w    = (const float*)d_in[5];
    const float* k_w    = (const float*)d_in[6];
    const float* v_w    = (const float*)d_in[7];
    const float* o_w    = (const float*)d_in[8];
    const float* ln1    = (const float*)d_in[9];
    const float* ln2    = (const float*)d_in[10];
    const float* gate_w = (const float*)d_in[11];
    const float* up_w   = (const float*)d_in[12];
    const float* gp_w   = (const float*)d_in[13];
    const float* down_w = (const float*)d_in[14];
    float* out = (float*)d_out;

    cudaFuncSetAttribute(tc_gemm, cudaFuncAttributeMaxDynamicSharedMemorySize, TCG_SMEM);
    cudaFuncSetAttribute(tc_gemm_upgate, cudaFuncAttributeMaxDynamicSharedMemorySize, UPG_SMEM);

    void *p_xn, *p_q, *p_attn, *p_x1, *p_xn2, *p_hup, *p_dout, *p_assign, *p_tilee;
    cudaGetSymbolAddress(&p_xn, g_xn);
    cudaGetSymbolAddress(&p_q, g_q);
    cudaGetSymbolAddress(&p_attn, g_attn);
    cudaGetSymbolAddress(&p_x1, g_x1);
    cudaGetSymbolAddress(&p_xn2, g_xn2);
    cudaGetSymbolAddress(&p_hup, g_Hup);
    cudaGetSymbolAddress(&p_dout, g_Dout);
    cudaGetSymbolAddress(&p_assign, g_assign);
    cudaGetSymbolAddress(&p_tilee, g_tilee);
    void *p_k, *p_v;
    cudaGetSymbolAddress(&p_k, g_k);
    cudaGetSymbolAddress(&p_v, g_v);

    float* xn   = (float*)p_xn;
    float* qb   = (float*)p_q;
    float* kb   = (float*)p_k;
    float* vb   = (float*)p_v;
    float* at   = (float*)p_attn;
    float* x1   = (float*)p_x1;
    float* xn2  = (float*)p_xn2;
    float* hup  = (float*)p_hup;
    float* dout = (float*)p_dout;
    int* assign = (int*)p_assign;
    int* tilee  = (int*)p_tilee;

    rmsnorm_kernel<<<SEQ, 256>>>(hidden, ln1, xn);
    tc_gemm<<<dim3(8, 8), 512, TCG_SMEM>>>(xn, HID, q_w, NH * HD, nullptr,
                                           qb, NH * HD, HID, nullptr, 0);
    tc_gemm<<<dim3(2, 8), 512, TCG_SMEM>>>(xn, HID, k_w, KVH * HD, nullptr,
                                           kb, KVH * HD, HID, nullptr, 0);
    tc_gemm<<<dim3(2, 8), 512, TCG_SMEM>>>(xn, HID, v_w, KVH * HD, nullptr,
                                           vb, KVH * HD, HID, nullptr, 0);
    rope_kernel<<<dim3(SEQ, NH + KVH), HD>>>(cosb, sinb);
    attn_scores_kernel<<<dim3(16, 16, NH), 256>>>();
    softmax_kernel<<<dim3(SEQ, NH), 256>>>();
    attn_pv_kernel<<<dim3(2, 16, NH), 256>>>();
    tc_gemm<<<dim3(8, 8), 512, TCG_SMEM>>>(at, HID, o_w, HID, hidden,
                                           x1, HID, HID, nullptr, 0);
    rmsnorm_kernel<<<SEQ, 256>>>(x1, ln2, xn2);
    route_kernel<<<SEQ, 256>>>(gate_w);
    group_kernel<<<1, 256>>>();
    tc_gemm_upgate<<<dim3(FDIM / 128, MTILES), 512, UPG_SMEM>>>(
        xn2, HID, up_w, gp_w, hup, assign, tilee, (long long)HID * FDIM);
    tc_gemm<<<dim3(HID / 256, MTILES), 512, TCG_SMEM>>>(
        hup, FDIM, down_w, HID, nullptr, dout, HID, FDIM,
        tilee, (long long)FDIM * HID);
    combine_kernel<<<SEQ, 256>>>(out);
}

// round 10
// speedup vs baseline: 2.2718x; 2.2718x over previous
#include <cuda_runtime.h>
#include <cuda_fp16.h>
#include <math.h>
#include <stdint.h>

// ---------------- problem constants ----------------
#define SEQ   1024
#define HID   2048
#define NH    16
#define KVH   4
#define HD    128
#define FDIM  7168
#define NEXP  8
#define PADROWS 3072
#define MTILES  24
#define EPSV  1e-5f
#define SCALE 0.08838834764831845f

// ---------------- device scratch ----------------
__device__ float g_xn  [SEQ*HID];
__device__ float g_q   [SEQ*NH*HD];
__device__ float g_k   [SEQ*KVH*HD];
__device__ float g_v   [SEQ*KVH*HD];
__device__ float g_P   [(size_t)NH*SEQ*SEQ];
__device__ float g_attn[SEQ*HID];
__device__ float g_x1  [SEQ*HID];
__device__ float g_xn2 [SEQ*HID];
__device__ float g_Hup [(size_t)PADROWS*FDIM];
__device__ float g_Dout[(size_t)PADROWS*HID];
__device__ float g_topw[SEQ*2];
__device__ int   g_topi[SEQ*2];
__device__ int   g_assign[PADROWS];
__device__ int   g_tilee[MTILES];
__device__ int   g_slot[SEQ*2];

// ---------------- fp16 mma helpers ----------------
__device__ __forceinline__ uint32_t smem_u32(const void* p) {
    uint32_t a;
    asm("{ .reg .u64 t; cvta.to.shared.u64 t, %1; cvt.u32.u64 %0, t; }" : "=r"(a) : "l"(p));
    return a;
}
__device__ __forceinline__ uint32_t pack_h2(float x, float y) {
    __half2 h = __floats2half2_rn(x, y);
    return *reinterpret_cast<uint32_t*>(&h);
}
__device__ __forceinline__ void ldsm_x4(uint32_t& r0, uint32_t& r1, uint32_t& r2,
                                        uint32_t& r3, uint32_t addr) {
    asm volatile("ldmatrix.sync.aligned.m8n8.x4.shared.b16 {%0,%1,%2,%3}, [%4];"
                 : "=r"(r0), "=r"(r1), "=r"(r2), "=r"(r3) : "r"(addr));
}
__device__ __forceinline__ void ldsm_x4t(uint32_t& r0, uint32_t& r1, uint32_t& r2,
                                         uint32_t& r3, uint32_t addr) {
    asm volatile("ldmatrix.sync.aligned.m8n8.x4.trans.shared.b16 {%0,%1,%2,%3}, [%4];"
                 : "=r"(r0), "=r"(r1), "=r"(r2), "=r"(r3) : "r"(addr));
}
__device__ __forceinline__ void mma_f16(float* c, uint32_t a0, uint32_t a1,
                                        uint32_t a2, uint32_t a3,
                                        uint32_t b0, uint32_t b1) {
    asm volatile(
        "mma.sync.aligned.m16n8k16.row.col.f32.f16.f16.f32 "
        "{%0,%1,%2,%3}, {%4,%5,%6,%7}, {%8,%9}, {%0,%1,%2,%3};"
        : "+f"(c[0]), "+f"(c[1]), "+f"(c[2]), "+f"(c[3])
        : "r"(a0), "r"(a1), "r"(a2), "r"(a3), "r"(b0), "r"(b1));
}

// A smem: [128 rows][32 k halves], 64B/row, 16B-chunk swizzle c^=((row>>1)&3)
__device__ __forceinline__ int offA(int row, int k) {
    return row * 64 + ((((k >> 3) ^ (row >> 1)) & 3) << 4) + ((k & 7) << 1);
}
// B smem: [32 k rows][128 n halves], 256B/row, 16B-chunk swizzle c^=(k&7)
__device__ __forceinline__ int offB(int k, int n) {
    return k * 256 + ((((n >> 3) ^ k) & 15) << 4) + ((n & 7) << 1);
}

#define ATB 8192
#define BTB 8192
#define HG_SMEM  (512 + 2*ATB + 2*BTB)   // 33.3 KB
#define UPG_SMEM (512 + 2*ATB + 4*BTB)   // 49.7 KB

// ============ fp16 GEMM: C[M,N] = A@B (+Dadd); 256 thr, block 128x128, warp 64x32 ============
__global__ __launch_bounds__(256, 2)
void hgemm(const float* __restrict__ A, int lda,
           const float* __restrict__ B, int ldb,
           const float* __restrict__ Dadd,
           float* __restrict__ C, int ldc, int K,
           const int* __restrict__ ridx,
           const int* __restrict__ tilee, long long bstride)
{
    extern __shared__ char smc[];
    int* ridx_sm = (int*)smc;
    char* sA = smc + 512;
    char* sB = smc + 512 + 2 * ATB;

    const int m0 = blockIdx.y * 128, n0 = blockIdx.x * 128;
    if (tilee) {
        int e = tilee[blockIdx.y];
        if (e < 0) return;
        B += (size_t)e * bstride;
    }

    const int tid = threadIdx.x, lane = tid & 31, wid = tid >> 5;
    const int wm = wid & 1, wn = wid >> 1;     // 2x4 warp grid, 64x32 tiles
    const int grp = lane >> 2, qid = lane & 3;

    if (ridx) {
        if (tid < 128) ridx_sm[tid] = ridx[m0 + tid];
        __syncthreads();
    }

    const uint32_t sAu = smem_u32(sA), sBu = smem_u32(sB);

    // staging indices
    int ar[4], ak[4], bk[4], bn[4];
#pragma unroll
    for (int i = 0; i < 4; i++) {
        int idx = i * 256 + tid;
        ar[i] = idx >> 3; ak[i] = (idx & 7) << 2;
        bk[i] = idx >> 5; bn[i] = (idx & 31) << 2;
    }

    // ldmatrix lane addresses (per buffer added later)
    const int aRow = lane & 15, aKoff = (lane >> 4) << 3;
    const int lK = lane & 7, mv = lane >> 3;
    const int bKoff = (mv & 1) << 3, bNoff = (mv >> 1) << 3;

    float acc[4][4][4] = {};
    float4 ra[4], rb[4];
    const int nk = K >> 5;

    auto load_stage = [&](int kt) {
        const int k0 = kt << 5;
#pragma unroll
        for (int i = 0; i < 4; i++) {
            if (ridx) {
                int r = ridx_sm[ar[i]];
                ra[i] = (r >= 0) ? *(const float4*)(A + (size_t)r * lda + k0 + ak[i])
                                 : make_float4(0.f, 0.f, 0.f, 0.f);
            } else {
                ra[i] = *(const float4*)(A + (size_t)(m0 + ar[i]) * lda + k0 + ak[i]);
            }
            rb[i] = *(const float4*)(B + (size_t)(k0 + bk[i]) * ldb + n0 + bn[i]);
        }
    };
    auto store_stage = [&](int b) {
        char* Ab = sA + b * ATB;
        char* Bb = sB + b * BTB;
#pragma unroll
        for (int i = 0; i < 4; i++) {
            uint2 va = { pack_h2(ra[i].x, ra[i].y), pack_h2(ra[i].z, ra[i].w) };
            *(uint2*)(Ab + offA(ar[i], ak[i])) = va;
            uint2 vb = { pack_h2(rb[i].x, rb[i].y), pack_h2(rb[i].z, rb[i].w) };
            *(uint2*)(Bb + offB(bk[i], bn[i])) = vb;
        }
    };

    load_stage(0);
    store_stage(0);
    __syncthreads();

    for (int kt = 0; kt < nk; kt++) {
        if (kt + 1 < nk) load_stage(kt + 1);

        const uint32_t aB = sAu + (kt & 1) * ATB;
        const uint32_t bB = sBu + (kt & 1) * BTB;
#pragma unroll
        for (int s = 0; s < 2; s++) {
            uint32_t b[2][4];
#pragma unroll
            for (int g = 0; g < 2; g++)
                ldsm_x4t(b[g][0], b[g][1], b[g][2], b[g][3],
                         bB + offB(s * 16 + bKoff + lK, wn * 32 + g * 16 + bNoff));
#pragma unroll
            for (int i = 0; i < 4; i++) {
                uint32_t a0, a1, a2, a3;
                ldsm_x4(a0, a1, a2, a3,
                        aB + offA(wm * 64 + i * 16 + aRow, s * 16 + aKoff));
                mma_f16(acc[i][0], a0, a1, a2, a3, b[0][0], b[0][1]);
                mma_f16(acc[i][1], a0, a1, a2, a3, b[0][2], b[0][3]);
                mma_f16(acc[i][2], a0, a1, a2, a3, b[1][0], b[1][1]);
                mma_f16(acc[i][3], a0, a1, a2, a3, b[1][2], b[1][3]);
            }
        }

        if (kt + 1 < nk) store_stage((kt + 1) & 1);
        __syncthreads();
    }

#pragma unroll
    for (int i = 0; i < 4; i++) {
#pragma unroll
        for (int j = 0; j < 4; j++) {
            int r0 = m0 + wm * 64 + i * 16 + grp;
            int r1 = r0 + 8;
            int c  = n0 + wn * 32 + j * 8 + qid * 2;
            float2 v0 = { acc[i][j][0], acc[i][j][1] };
            float2 v1 = { acc[i][j][2], acc[i][j][3] };
            if (Dadd) {
                float2 d0 = *(const float2*)(Dadd + (size_t)r0 * ldc + c);
                float2 d1 = *(const float2*)(Dadd + (size_t)r1 * ldc + c);
                v0.x += d0.x; v0.y += d0.y;
                v1.x += d1.x; v1.y += d1.y;
            }
            *(float2*)(C + (size_t)r0 * ldc + c) = v0;
            *(float2*)(C + (size_t)r1 * ldc + c) = v1;
        }
    }
}

// ============ fused upgate: 512 thr, block 128x128, warp 32x32, dual B + SiLU ============
__global__ __launch_bounds__(512, 1)
void hgemm_upgate(const float* __restrict__ A, int lda,
                  const float* __restrict__ B1, const float* __restrict__ B2,
                  float* __restrict__ C,
                  const int* __restrict__ ridx,
                  const int* __restrict__ tilee, long long bstride)
{
    extern __shared__ char smc[];
    int* ridx_sm = (int*)smc;
    char* sA  = smc + 512;
    char* sB1 = smc + 512 + 2 * ATB;
    char* sB2 = smc + 512 + 2 * ATB + 2 * BTB;

    const int m0 = blockIdx.y * 128, n0 = blockIdx.x * 128;
    int e = tilee[blockIdx.y];
    if (e < 0) return;
    B1 += (size_t)e * bstride;
    B2 += (size_t)e * bstride;

    const int tid = threadIdx.x, lane = tid & 31, wid = tid >> 5;
    const int wm = wid & 3, wn = wid >> 2;     // 4x4 warp grid, 32x32 tiles
    const int grp = lane >> 2, qid = lane & 3;

    if (tid < 128) ridx_sm[tid] = ridx[m0 + tid];
    __syncthreads();

    const uint32_t sAu = smem_u32(sA), sB1u = smem_u32(sB1), sB2u = smem_u32(sB2);

    int ar[2], ak[2], bk[2], bn[2];
#pragma unroll
    for (int i = 0; i < 2; i++) {
        int idx = i * 512 + tid;
        ar[i] = idx >> 3; ak[i] = (idx & 7) << 2;
        bk[i] = idx >> 5; bn[i] = (idx & 31) << 2;
    }

    const int aRow = lane & 15, aKoff = (lane >> 4) << 3;
    const int lK = lane & 7, mv = lane >> 3;
    const int bKoff = (mv & 1) << 3, bNoff = (mv >> 1) << 3;

    float acc1[2][4][4] = {}, acc2[2][4][4] = {};
    float4 ra[2], rb1[2], rb2[2];
    const int nk = HID >> 5;

    auto load_stage = [&](int kt) {
        const int k0 = kt << 5;
#pragma unroll
        for (int i = 0; i < 2; i++) {
            int r = ridx_sm[ar[i]];
            ra[i] = (r >= 0) ? *(const float4*)(A + (size_t)r * lda + k0 + ak[i])
                             : make_float4(0.f, 0.f, 0.f, 0.f);
            rb1[i] = *(const float4*)(B1 + (size_t)(k0 + bk[i]) * FDIM + n0 + bn[i]);
            rb2[i] = *(const float4*)(B2 + (size_t)(k0 + bk[i]) * FDIM + n0 + bn[i]);
        }
    };
    auto store_stage = [&](int b) {
        char* Ab  = sA + b * ATB;
        char* B1b = sB1 + b * BTB;
        char* B2b = sB2 + b * BTB;
#pragma unroll
        for (int i = 0; i < 2; i++) {
            uint2 va = { pack_h2(ra[i].x, ra[i].y), pack_h2(ra[i].z, ra[i].w) };
            *(uint2*)(Ab + offA(ar[i], ak[i])) = va;
            uint2 v1 = { pack_h2(rb1[i].x, rb1[i].y), pack_h2(rb1[i].z, rb1[i].w) };
            *(uint2*)(B1b + offB(bk[i], bn[i])) = v1;
            uint2 v2 = { pack_h2(rb2[i].x, rb2[i].y), pack_h2(rb2[i].z, rb2[i].w) };
            *(uint2*)(B2b + offB(bk[i], bn[i])) = v2;
        }
    };

    load_stage(0);
    store_stage(0);
    __syncthreads();

    for (int kt = 0; kt < nk; kt++) {
        if (kt + 1 < nk) load_stage(kt + 1);

        const uint32_t aB  = sAu + (kt & 1) * ATB;
        const uint32_t b1B = sB1u + (kt & 1) * BTB;
        const uint32_t b2B = sB2u + (kt & 1) * BTB;
#pragma unroll
        for (int s = 0; s < 2; s++) {
            uint32_t u[2][4], g[2][4];
#pragma unroll
            for (int gg = 0; gg < 2; gg++) {
                int bo = offB(s * 16 + bKoff + lK, wn * 32 + gg * 16 + bNoff);
                ldsm_x4t(u[gg][0], u[gg][1], u[gg][2], u[gg][3], b1B + bo);
                ldsm_x4t(g[gg][0], g[gg][1], g[gg][2], g[gg][3], b2B + bo);
            }
#pragma unroll
            for (int i = 0; i < 2; i++) {
                uint32_t a0, a1, a2, a3;
                ldsm_x4(a0, a1, a2, a3,
                        aB + offA(wm * 32 + i * 16 + aRow, s * 16 + aKoff));
                mma_f16(acc1[i][0], a0, a1, a2, a3, u[0][0], u[0][1]);
                mma_f16(acc1[i][1], a0, a1, a2, a3, u[0][2], u[0][3]);
                mma_f16(acc1[i][2], a0, a1, a2, a3, u[1][0], u[1][1]);
                mma_f16(acc1[i][3], a0, a1, a2, a3, u[1][2], u[1][3]);
                mma_f16(acc2[i][0], a0, a1, a2, a3, g[0][0], g[0][1]);
                mma_f16(acc2[i][1], a0, a1, a2, a3, g[0][2], g[0][3]);
                mma_f16(acc2[i][2], a0, a1, a2, a3, g[1][0], g[1][1]);
                mma_f16(acc2[i][3], a0, a1, a2, a3, g[1][2], g[1][3]);
            }
        }

        if (kt + 1 < nk) store_stage((kt + 1) & 1);
        __syncthreads();
    }

#pragma unroll
    for (int i = 0; i < 2; i++) {
#pragma unroll
        for (int j = 0; j < 4; j++) {
            int r0 = m0 + wm * 32 + i * 16 + grp;
            int r1 = r0 + 8;
            int c  = n0 + wn * 32 + j * 8 + qid * 2;
            float uu, gg;
            float2 v0, v1;
            uu = acc1[i][j][0]; gg = acc2[i][j][0]; v0.x = (uu / (1.f + expf(-uu))) * gg;
            uu = acc1[i][j][1]; gg = acc2[i][j][1]; v0.y = (uu / (1.f + expf(-uu))) * gg;
            uu = acc1[i][j][2]; gg = acc2[i][j][2]; v1.x = (uu / (1.f + expf(-uu))) * gg;
            uu = acc1[i][j][3]; gg = acc2[i][j][3]; v1.y = (uu / (1.f + expf(-uu))) * gg;
            *(float2*)(C + (size_t)r0 * FDIM + c) = v0;
            *(float2*)(C + (size_t)r1 * FDIM + c) = v1;
        }
    }
}

// ---------------- RMSNorm ----------------
__global__ void rmsnorm_kernel(const float* __restrict__ x, const float* __restrict__ w,
                               float* __restrict__ y)
{
    int t = blockIdx.x;
    const float* xr = x + (size_t)t * HID;
    float ss = 0.f;
    for (int j = threadIdx.x; j < HID; j += 256) { float v = xr[j]; ss += v * v; }
    __shared__ float sm[256];
    sm[threadIdx.x] = ss; __syncthreads();
    for (int o = 128; o > 0; o >>= 1) {
        if (threadIdx.x < o) sm[threadIdx.x] += sm[threadIdx.x + o];
        __syncthreads();
    }
    float inv = rsqrtf(sm[0] / (float)HID + EPSV);
    for (int j = threadIdx.x; j < HID; j += 256)
        y[(size_t)t * HID + j] = w[j] * (xr[j] * inv);
}

// ---------------- RoPE ----------------
__global__ void rope_kernel(const float* __restrict__ cosb, const float* __restrict__ sinb)
{
    int t = blockIdx.x, hh = blockIdx.y, d = threadIdx.x;
    float* p = (hh < NH) ? (g_q + (size_t)t * NH * HD + hh * HD)
                         : (g_k + (size_t)t * KVH * HD + (hh - NH) * HD);
    __shared__ float buf[HD];
    float x = p[d];
    buf[d] = x;
    __syncthreads();
    float rot = (d < HD / 2) ? -buf[d + HD / 2] : buf[d - HD / 2];
    p[d] = x * cosb[t * HD + d] + rot * sinb[t * HD + d];
}

// ---------------- scores ----------------
__global__ __launch_bounds__(256)
void attn_scores_kernel()
{
    const int h = blockIdx.z;
    const int m0 = blockIdx.y * 64, n0 = blockIdx.x * 64;
    if (n0 > m0 + 63) return;
    const float* A  = g_q + h * HD;
    const float* Bm = g_k + (h >> 2) * HD;
    float* C = g_P + (size_t)h * SEQ * SEQ;
    __shared__ float As[16][65];
    __shared__ float Bs[16][65];
    const int tid = threadIdx.x;
    const int tx = tid & 15, ty = tid >> 4;
    const int a_m = tid >> 2, a_k = (tid & 3) << 2;
    float acc[4][4] = {};
    for (int k0 = 0; k0 < HD; k0 += 16) {
        float4 av = *(const float4*)(A + (size_t)(m0 + a_m) * (NH * HD) + k0 + a_k);
        As[a_k + 0][a_m] = av.x; As[a_k + 1][a_m] = av.y;
        As[a_k + 2][a_m] = av.z; As[a_k + 3][a_m] = av.w;
        float4 bv = *(const float4*)(Bm + (size_t)(n0 + a_m) * (KVH * HD) + k0 + a_k);
        Bs[a_k + 0][a_m] = bv.x; Bs[a_k + 1][a_m] = bv.y;
        Bs[a_k + 2][a_m] = bv.z; Bs[a_k + 3][a_m] = bv.w;
        __syncthreads();
#pragma unroll
        for (int kk = 0; kk < 16; kk++) {
            float a[4], b[4];
#pragma unroll
            for (int i = 0; i < 4; i++) a[i] = As[kk][ty * 4 + i];
#pragma unroll
            for (int j = 0; j < 4; j++) b[j] = Bs[kk][tx * 4 + j];
#pragma unroll
            for (int i = 0; i < 4; i++)
#pragma unroll
                for (int j = 0; j < 4; j++)
                    acc[i][j] = fmaf(a[i], b[j], acc[i][j]);
        }
        __syncthreads();
    }
#pragma unroll
    for (int i = 0; i < 4; i++) {
        size_t off = (size_t)(m0 + ty * 4 + i) * SEQ + n0 + tx * 4;
        float4 r = { acc[i][0] * SCALE, acc[i][1] * SCALE, acc[i][2] * SCALE, acc[i][3] * SCALE };
        *(float4*)(C + off) = r;
    }
}

// ---------------- softmax ----------------
__global__ void softmax_kernel()
{
    int t = blockIdx.x, h = blockIdx.y, tid = threadIdx.x;
    float* row = g_P + ((size_t)h * SEQ + t) * SEQ;
    int n = t + 1;
    __shared__ float sm[256];
    float mx = -1e30f;
    for (int j = tid; j < n; j += 256) mx = fmaxf(mx, row[j]);
    sm[tid] = mx; __syncthreads();
    for (int o = 128; o > 0; o >>= 1) {
        if (tid < o) sm[tid] = fmaxf(sm[tid], sm[tid + o]);
        __syncthreads();
    }
    float m = sm[0];
    __syncthreads();
    float sum = 0.f;
    for (int j = tid; j < n; j += 256) {
        float e = expf(row[j] - m);
        row[j] = e;
        sum += e;
    }
    sm[tid] = sum; __syncthreads();
    for (int o = 128; o > 0; o >>= 1) {
        if (tid < o) sm[tid] += sm[tid + o];
        __syncthreads();
    }
    float inv = 1.f / sm[0];
    for (int j = tid; j < SEQ; j += 256)
        row[j] = (j < n) ? row[j] * inv : 0.f;
}

// ---------------- attn = P @ V ----------------
__global__ __launch_bounds__(256)
void attn_pv_kernel()
{
    const int h = blockIdx.z;
    const int m0 = blockIdx.y * 64, n0 = blockIdx.x * 64;
    const float* A = g_P + (size_t)h * SEQ * SEQ;
    const float* B = g_v + (h >> 2) * HD;
    float* C = g_attn + h * HD;
    const int kend = m0 + 64;
    __shared__ float As[16][65];
    __shared__ float Bs[16][64];
    const int tid = threadIdx.x;
    const int tx = tid & 15, ty = tid >> 4;
    const int a_m = tid >> 2, a_k = (tid & 3) << 2;
    const int b_k = tid >> 4, b_n = (tid & 15) << 2;
    float acc[4][4] = {};
    for (int k0 = 0; k0 < kend; k0 += 16) {
        float4 av = *(const float4*)(A + (size_t)(m0 + a_m) * SEQ + k0 + a_k);
        As[a_k + 0][a_m] = av.x; As[a_k + 1][a_m] = av.y;
        As[a_k + 2][a_m] = av.z; As[a_k + 3][a_m] = av.w;
        *(float4*)&Bs[b_k][b_n] = *(const float4*)(B + (size_t)(k0 + b_k) * (KVH * HD) + n0 + b_n);
        __syncthreads();
#pragma unroll
        for (int kk = 0; kk < 16; kk++) {
            float a[4];
#pragma unroll
            for (int i = 0; i < 4; i++) a[i] = As[kk][ty * 4 + i];
            float4 bv = *(const float4*)&Bs[kk][tx * 4];
            float b[4] = { bv.x, bv.y, bv.z, bv.w };
#pragma unroll
            for (int i = 0; i < 4; i++)
#pragma unroll
                for (int j = 0; j < 4; j++)
                    acc[i][j] = fmaf(a[i], b[j], acc[i][j]);
        }
        __syncthreads();
    }
#pragma unroll
    for (int i = 0; i < 4; i++) {
        size_t off = (size_t)(m0 + ty * 4 + i) * HID + n0 + tx * 4;
        float4 r = { acc[i][0], acc[i][1], acc[i][2], acc[i][3] };
        *(float4*)(C + off) = r;
    }
}

// ---------------- routing ----------------
__global__ void route_kernel(const float* __restrict__ gw)
{
    int t = blockIdx.x, tid = threadIdx.x;
    float acc[8] = {};
    for (int hh = tid; hh < HID; hh += 256) {
        float xv = g_xn2[(size_t)t * HID + hh];
        const float* gr = gw + hh * 8;
        float4 a0 = *(const float4*)gr, a1 = *(const float4*)(gr + 4);
        acc[0] += xv * a0.x; acc[1] += xv * a0.y; acc[2] += xv * a0.z; acc[3] += xv * a0.w;
        acc[4] += xv * a1.x; acc[5] += xv * a1.y; acc[6] += xv * a1.z; acc[7] += xv * a1.w;
    }
#pragma unroll
    for (int o = 16; o > 0; o >>= 1)
#pragma unroll
        for (int e = 0; e < 8; e++)
            acc[e] += __shfl_down_sync(0xffffffffu, acc[e], o);
    __shared__ float sm[8][8];
    int w = tid >> 5, lane = tid & 31;
    if (lane == 0)
#pragma unroll
        for (int e = 0; e < 8; e++) sm[w][e] = acc[e];
    __syncthreads();
    if (tid == 0) {
        float l[8];
        for (int e = 0; e < 8; e++) {
            float s = 0.f;
            for (int ww = 0; ww < 8; ww++) s += sm[ww][e];
            l[e] = s;
        }
        int i0 = 0;
        for (int e = 1; e < 8; e++) if (l[e] > l[i0]) i0 = e;
        int i1 = -1;
        for (int e = 0; e < 8; e++) if (e != i0 && (i1 < 0 || l[e] > l[i1])) i1 = e;
        float p0 = 1.f, p1 = expf(l[i1] - l[i0]);
        float s = p0 + p1;
        g_topi[t * 2] = i0; g_topi[t * 2 + 1] = i1;
        g_topw[t * 2] = p0 / s; g_topw[t * 2 + 1] = p1 / s;
    }
}

// ---------------- grouping ----------------
__global__ void group_kernel()
{
    int tid = threadIdx.x;
    for (int i = tid; i < PADROWS; i += 256) g_assign[i] = -1;
    if (tid < MTILES) g_tilee[tid] = -1;
    __shared__ int cnt[NEXP], off[NEXP];
    if (tid < NEXP) cnt[tid] = 0;
    __syncthreads();
    for (int a = tid; a < SEQ * 2; a += 256) atomicAdd(&cnt[g_topi[a]], 1);
    __syncthreads();
    if (tid == 0) {
        int cur = 0;
        for (int e = 0; e < NEXP; e++) {
            off[e] = cur;
            int tiles = (cnt[e] + 127) >> 7;
            for (int tt = 0; tt < tiles; tt++) g_tilee[(cur >> 7) + tt] = e;
            cur += tiles * 128;
        }
    }
    __syncthreads();
    int w = tid >> 5, lane = tid & 31;
    if (w < NEXP) {
        int e = w, base = off[e], filled = 0;
        for (int a0 = 0; a0 < SEQ * 2; a0 += 32) {
            int a = a0 + lane;
            int ti = g_topi[a];
            bool match = (ti == e);
            unsigned msk = __ballot_sync(0xffffffffu, match);
            if (match) {
                int rank = __popc(msk & ((1u << lane) - 1u));
                int slot = base + filled + rank;
                g_assign[slot] = a >> 1;
                g_slot[a] = slot;
            }
            filled += __popc(msk);
        }
    }
}

// ---------------- combine ----------------
__global__ void combine_kernel(float* __restrict__ out)
{
    int t = blockIdx.x;
    int s0 = g_slot[t * 2], s1 = g_slot[t * 2 + 1];
    float w0 = g_topw[t * 2], w1 = g_topw[t * 2 + 1];
    for (int j = threadIdx.x; j < HID; j += 256) {
        size_t o = (size_t)t * HID + j;
        out[o] = g_x1[o] + w0 * g_Dout[(size_t)s0 * HID + j]
                         + w1 * g_Dout[(size_t)s1 * HID + j];
    }
}

// ---------------- launch ----------------
extern "C" void kernel_launch(void* const* d_in, const int* in_sizes, int n_in,
                              void* d_out, int out_size)
{
    const float* hidden = (const float*)d_in[0];
    const float* cosb   = (const float*)d_in[1];
    const float* sinb   = (const float*)d_in[2];
    const float* q_w    = (const float*)d_in[5];
    const float* k_w    = (const float*)d_in[6];
    const float* v_w    = (const float*)d_in[7];
    const float* o_w    = (const float*)d_in[8];
    const float* ln1    = (const float*)d_in[9];
    const float* ln2    = (const float*)d_in[10];
    const float* gate_w = (const float*)d_in[11];
    const float* up_w   = (const float*)d_in[12];
    const float* gp_w   = (const float*)d_in[13];
    const float* down_w = (const float*)d_in[14];
    float* out = (float*)d_out;

    cudaFuncSetAttribute(hgemm,        cudaFuncAttributeMaxDynamicSharedMemorySize, HG_SMEM);
    cudaFuncSetAttribute(hgemm_upgate, cudaFuncAttributeMaxDynamicSharedMemorySize, UPG_SMEM);

    void *p_xn, *p_q, *p_attn, *p_x1, *p_xn2, *p_hup, *p_dout, *p_assign, *p_tilee;
    cudaGetSymbolAddress(&p_xn, g_xn);
    cudaGetSymbolAddress(&p_q, g_q);
    cudaGetSymbolAddress(&p_attn, g_attn);
    cudaGetSymbolAddress(&p_x1, g_x1);
    cudaGetSymbolAddress(&p_xn2, g_xn2);
    cudaGetSymbolAddress(&p_hup, g_Hup);
    cudaGetSymbolAddress(&p_dout, g_Dout);
    cudaGetSymbolAddress(&p_assign, g_assign);
    cudaGetSymbolAddress(&p_tilee, g_tilee);
    void *p_k, *p_v;
    cudaGetSymbolAddress(&p_k, g_k);
    cudaGetSymbolAddress(&p_v, g_v);

    float* xn   = (float*)p_xn;
    float* qb   = (float*)p_q;
    float* kb   = (float*)p_k;
    float* vb   = (float*)p_v;
    float* at   = (float*)p_attn;
    float* x1   = (float*)p_x1;
    float* xn2  = (float*)p_xn2;
    float* hup  = (float*)p_hup;
    float* dout = (float*)p_dout;
    int* assign = (int*)p_assign;
    int* tilee  = (int*)p_tilee;

    rmsnorm_kernel<<<SEQ, 256>>>(hidden, ln1, xn);
    hgemm<<<dim3(16, 8), 256, HG_SMEM>>>(xn, HID, q_w, NH * HD, nullptr,
                                         qb, NH * HD, HID, nullptr, nullptr, 0);
    hgemm<<<dim3(4, 8), 256, HG_SMEM>>>(xn, HID, k_w, KVH * HD, nullptr,
                                        kb, KVH * HD, HID, nullptr, nullptr, 0);
    hgemm<<<dim3(4, 8), 256, HG_SMEM>>>(xn, HID, v_w, KVH * HD, nullptr,
                                        vb, KVH * HD, HID, nullptr, nullptr, 0);
    rope_kernel<<<dim3(SEQ, NH + KVH), HD>>>(cosb, sinb);
    attn_scores_kernel<<<dim3(16, 16, NH), 256>>>();
    softmax_kernel<<<dim3(SEQ, NH), 256>>>();
    attn_pv_kernel<<<dim3(2, 16, NH), 256>>>();
    hgemm<<<dim3(16, 8), 256, HG_SMEM>>>(at, HID, o_w, HID, hidden,
                                         x1, HID, HID, nullptr, nullptr, 0);
    rmsnorm_kernel<<<SEQ, 256>>>(x1, ln2, xn2);
    route_kernel<<<SEQ, 256>>>(gate_w);
    group_kernel<<<1, 256>>>();
    hgemm_upgate<<<dim3(FDIM / 128, MTILES), 512, UPG_SMEM>>>(
        xn2, HID, up_w, gp_w, hup, assign, tilee, (long long)HID * FDIM);
    hgemm<<<dim3(16, MTILES), 256, HG_SMEM>>>(
        hup, FDIM, down_w, HID, nullptr, dout, HID, FDIM,
        nullptr, tilee, (long long)FDIM * HID);
    combine_kernel<<<SEQ, 256>>>(out);
}

// round 11
// speedup vs baseline: 2.6806x; 1.1799x over previous
#include <cuda_runtime.h>
#include <cuda_fp16.h>
#include <math.h>
#include <stdint.h>

// ---------------- problem constants ----------------
#define SEQ   1024
#define HID   2048
#define NH    16
#define KVH   4
#define HD    128
#define FDIM  7168
#define NEXP  8
#define PADROWS 3072
#define MTILES  24
#define EPSV  1e-5f
#define SCALE 0.08838834764831845f

// ---------------- device scratch ----------------
__device__ float g_xn  [SEQ*HID];
__device__ float g_q   [SEQ*NH*HD];
__device__ float g_k   [SEQ*KVH*HD];
__device__ float g_v   [SEQ*KVH*HD];
__device__ __half g_Ph [(size_t)NH*SEQ*SEQ];   // fp16 scores/probs (32 MB)
__device__ float g_attn[SEQ*HID];
__device__ float g_x1  [SEQ*HID];
__device__ float g_xn2 [SEQ*HID];
__device__ float g_Hup [(size_t)PADROWS*FDIM];
__device__ float g_Dout[(size_t)PADROWS*HID];
__device__ float g_topw[SEQ*2];
__device__ int   g_topi[SEQ*2];
__device__ int   g_assign[PADROWS];
__device__ int   g_tilee[MTILES];
__device__ int   g_slot[SEQ*2];

// ---------------- fp16 mma helpers ----------------
__device__ __forceinline__ uint32_t smem_u32(const void* p) {
    uint32_t a;
    asm("{ .reg .u64 t; cvta.to.shared.u64 t, %1; cvt.u32.u64 %0, t; }" : "=r"(a) : "l"(p));
    return a;
}
__device__ __forceinline__ uint32_t pack_h2(float x, float y) {
    __half2 h = __floats2half2_rn(x, y);
    return *reinterpret_cast<uint32_t*>(&h);
}
__device__ __forceinline__ void ldsm_x4(uint32_t& r0, uint32_t& r1, uint32_t& r2,
                                        uint32_t& r3, uint32_t addr) {
    asm volatile("ldmatrix.sync.aligned.m8n8.x4.shared.b16 {%0,%1,%2,%3}, [%4];"
                 : "=r"(r0), "=r"(r1), "=r"(r2), "=r"(r3) : "r"(addr));
}
__device__ __forceinline__ void ldsm_x4t(uint32_t& r0, uint32_t& r1, uint32_t& r2,
                                         uint32_t& r3, uint32_t addr) {
    asm volatile("ldmatrix.sync.aligned.m8n8.x4.trans.shared.b16 {%0,%1,%2,%3}, [%4];"
                 : "=r"(r0), "=r"(r1), "=r"(r2), "=r"(r3) : "r"(addr));
}
__device__ __forceinline__ void mma_f16(float* c, uint32_t a0, uint32_t a1,
                                        uint32_t a2, uint32_t a3,
                                        uint32_t b0, uint32_t b1) {
    asm volatile(
        "mma.sync.aligned.m16n8k16.row.col.f32.f16.f16.f32 "
        "{%0,%1,%2,%3}, {%4,%5,%6,%7}, {%8,%9}, {%0,%1,%2,%3};"
        : "+f"(c[0]), "+f"(c[1]), "+f"(c[2]), "+f"(c[3])
        : "r"(a0), "r"(a1), "r"(a2), "r"(a3), "r"(b0), "r"(b1));
}

// A smem: [128 rows][32 k halves], 64B/row, 16B-chunk swizzle c^=((row>>1)&3)
__device__ __forceinline__ int offA(int row, int k) {
    return row * 64 + ((((k >> 3) ^ (row >> 1)) & 3) << 4) + ((k & 7) << 1);
}
// B smem: [32 k rows][128 n halves], 256B/row, 16B-chunk swizzle c^=(k&7)
__device__ __forceinline__ int offB(int k, int n) {
    return k * 256 + ((((n >> 3) ^ k) & 15) << 4) + ((n & 7) << 1);
}

#define ATB 8192
#define BTB 8192
#define HG_SMEM  (512 + 2*ATB + 2*BTB)   // 33.3 KB
#define UPG_SMEM (512 + 2*ATB + 4*BTB)   // 49.7 KB

// ============ fp16 GEMM: C[M,N] = A@B (+Dadd); 256 thr, block 128x128, warp 64x32 ============
__global__ __launch_bounds__(256, 2)
void hgemm(const float* __restrict__ A, int lda,
           const float* __restrict__ B, int ldb,
           const float* __restrict__ Dadd,
           float* __restrict__ C, int ldc, int K,
           const int* __restrict__ ridx,
           const int* __restrict__ tilee, long long bstride)
{
    extern __shared__ char smc[];
    int* ridx_sm = (int*)smc;
    char* sA = smc + 512;
    char* sB = smc + 512 + 2 * ATB;

    const int m0 = blockIdx.y * 128, n0 = blockIdx.x * 128;
    if (tilee) {
        int e = tilee[blockIdx.y];
        if (e < 0) return;
        B += (size_t)e * bstride;
    }

    const int tid = threadIdx.x, lane = tid & 31, wid = tid >> 5;
    const int wm = wid & 1, wn = wid >> 1;
    const int grp = lane >> 2, qid = lane & 3;

    if (ridx) {
        if (tid < 128) ridx_sm[tid] = ridx[m0 + tid];
        __syncthreads();
    }

    const uint32_t sAu = smem_u32(sA), sBu = smem_u32(sB);

    int ar[4], ak[4], bk[4], bn[4];
#pragma unroll
    for (int i = 0; i < 4; i++) {
        int idx = i * 256 + tid;
        ar[i] = idx >> 3; ak[i] = (idx & 7) << 2;
        bk[i] = idx >> 5; bn[i] = (idx & 31) << 2;
    }

    const int aRow = lane & 15, aKoff = (lane >> 4) << 3;
    const int lK = lane & 7, mv = lane >> 3;
    const int bKoff = (mv & 1) << 3, bNoff = (mv >> 1) << 3;

    float acc[4][4][4] = {};
    float4 ra[4], rb[4];
    const int nk = K >> 5;

    auto load_stage = [&](int kt) {
        const int k0 = kt << 5;
#pragma unroll
        for (int i = 0; i < 4; i++) {
            if (ridx) {
                int r = ridx_sm[ar[i]];
                ra[i] = (r >= 0) ? *(const float4*)(A + (size_t)r * lda + k0 + ak[i])
                                 : make_float4(0.f, 0.f, 0.f, 0.f);
            } else {
                ra[i] = *(const float4*)(A + (size_t)(m0 + ar[i]) * lda + k0 + ak[i]);
            }
            rb[i] = *(const float4*)(B + (size_t)(k0 + bk[i]) * ldb + n0 + bn[i]);
        }
    };
    auto store_stage = [&](int b) {
        char* Ab = sA + b * ATB;
        char* Bb = sB + b * BTB;
#pragma unroll
        for (int i = 0; i < 4; i++) {
            uint2 va = { pack_h2(ra[i].x, ra[i].y), pack_h2(ra[i].z, ra[i].w) };
            *(uint2*)(Ab + offA(ar[i], ak[i])) = va;
            uint2 vb = { pack_h2(rb[i].x, rb[i].y), pack_h2(rb[i].z, rb[i].w) };
            *(uint2*)(Bb + offB(bk[i], bn[i])) = vb;
        }
    };

    load_stage(0);
    store_stage(0);
    __syncthreads();

    for (int kt = 0; kt < nk; kt++) {
        if (kt + 1 < nk) load_stage(kt + 1);

        const uint32_t aB = sAu + (kt & 1) * ATB;
        const uint32_t bB = sBu + (kt & 1) * BTB;
#pragma unroll
        for (int s = 0; s < 2; s++) {
            uint32_t b[2][4];
#pragma unroll
            for (int g = 0; g < 2; g++)
                ldsm_x4t(b[g][0], b[g][1], b[g][2], b[g][3],
                         bB + offB(s * 16 + bKoff + lK, wn * 32 + g * 16 + bNoff));
#pragma unroll
            for (int i = 0; i < 4; i++) {
                uint32_t a0, a1, a2, a3;
                ldsm_x4(a0, a1, a2, a3,
                        aB + offA(wm * 64 + i * 16 + aRow, s * 16 + aKoff));
                mma_f16(acc[i][0], a0, a1, a2, a3, b[0][0], b[0][1]);
                mma_f16(acc[i][1], a0, a1, a2, a3, b[0][2], b[0][3]);
                mma_f16(acc[i][2], a0, a1, a2, a3, b[1][0], b[1][1]);
                mma_f16(acc[i][3], a0, a1, a2, a3, b[1][2], b[1][3]);
            }
        }

        if (kt + 1 < nk) store_stage((kt + 1) & 1);
        __syncthreads();
    }

#pragma unroll
    for (int i = 0; i < 4; i++) {
#pragma unroll
        for (int j = 0; j < 4; j++) {
            int r0 = m0 + wm * 64 + i * 16 + grp;
            int r1 = r0 + 8;
            int c  = n0 + wn * 32 + j * 8 + qid * 2;
            float2 v0 = { acc[i][j][0], acc[i][j][1] };
            float2 v1 = { acc[i][j][2], acc[i][j][3] };
            if (Dadd) {
                float2 d0 = *(const float2*)(Dadd + (size_t)r0 * ldc + c);
                float2 d1 = *(const float2*)(Dadd + (size_t)r1 * ldc + c);
                v0.x += d0.x; v0.y += d0.y;
                v1.x += d1.x; v1.y += d1.y;
            }
            *(float2*)(C + (size_t)r0 * ldc + c) = v0;
            *(float2*)(C + (size_t)r1 * ldc + c) = v1;
        }
    }
}

// ============ fused QKV: one launch, blockIdx.x selects q/k/v ============
__global__ __launch_bounds__(256, 2)
void hgemm_qkv(const float* __restrict__ A,
               const float* __restrict__ qw, const float* __restrict__ kw,
               const float* __restrict__ vw,
               float* __restrict__ qb, float* __restrict__ kb, float* __restrict__ vb)
{
    extern __shared__ char smc[];
    char* sA = smc + 512;
    char* sB = smc + 512 + 2 * ATB;

    const int bx = blockIdx.x;
    const int m0 = blockIdx.y * 128;
    const float* B; float* C; int ldbc, n0;
    if (bx < 16)      { B = qw; C = qb; ldbc = NH * HD;  n0 = bx * 128; }
    else if (bx < 20) { B = kw; C = kb; ldbc = KVH * HD; n0 = (bx - 16) * 128; }
    else              { B = vw; C = vb; ldbc = KVH * HD; n0 = (bx - 20) * 128; }

    const int tid = threadIdx.x, lane = tid & 31, wid = tid >> 5;
    const int wm = wid & 1, wn = wid >> 1;
    const int grp = lane >> 2, qid = lane & 3;

    const uint32_t sAu = smem_u32(sA), sBu = smem_u32(sB);

    int ar[4], ak[4], bk[4], bn[4];
#pragma unroll
    for (int i = 0; i < 4; i++) {
        int idx = i * 256 + tid;
        ar[i] = idx >> 3; ak[i] = (idx & 7) << 2;
        bk[i] = idx >> 5; bn[i] = (idx & 31) << 2;
    }
    const int aRow = lane & 15, aKoff = (lane >> 4) << 3;
    const int lK = lane & 7, mv = lane >> 3;
    const int bKoff = (mv & 1) << 3, bNoff = (mv >> 1) << 3;

    float acc[4][4][4] = {};
    float4 ra[4], rb[4];
    const int nk = HID >> 5;

    auto load_stage = [&](int kt) {
        const int k0 = kt << 5;
#pragma unroll
        for (int i = 0; i < 4; i++) {
            ra[i] = *(const float4*)(A + (size_t)(m0 + ar[i]) * HID + k0 + ak[i]);
            rb[i] = *(const float4*)(B + (size_t)(k0 + bk[i]) * ldbc + n0 + bn[i]);
        }
    };
    auto store_stage = [&](int b) {
        char* Ab = sA + b * ATB;
        char* Bb = sB + b * BTB;
#pragma unroll
        for (int i = 0; i < 4; i++) {
            uint2 va = { pack_h2(ra[i].x, ra[i].y), pack_h2(ra[i].z, ra[i].w) };
            *(uint2*)(Ab + offA(ar[i], ak[i])) = va;
            uint2 vb2 = { pack_h2(rb[i].x, rb[i].y), pack_h2(rb[i].z, rb[i].w) };
            *(uint2*)(Bb + offB(bk[i], bn[i])) = vb2;
        }
    };

    load_stage(0);
    store_stage(0);
    __syncthreads();

    for (int kt = 0; kt < nk; kt++) {
        if (kt + 1 < nk) load_stage(kt + 1);
        const uint32_t aB = sAu + (kt & 1) * ATB;
        const uint32_t bB = sBu + (kt & 1) * BTB;
#pragma unroll
        for (int s = 0; s < 2; s++) {
            uint32_t b[2][4];
#pragma unroll
            for (int g = 0; g < 2; g++)
                ldsm_x4t(b[g][0], b[g][1], b[g][2], b[g][3],
                         bB + offB(s * 16 + bKoff + lK, wn * 32 + g * 16 + bNoff));
#pragma unroll
            for (int i = 0; i < 4; i++) {
                uint32_t a0, a1, a2, a3;
                ldsm_x4(a0, a1, a2, a3,
                        aB + offA(wm * 64 + i * 16 + aRow, s * 16 + aKoff));
                mma_f16(acc[i][0], a0, a1, a2, a3, b[0][0], b[0][1]);
                mma_f16(acc[i][1], a0, a1, a2, a3, b[0][2], b[0][3]);
                mma_f16(acc[i][2], a0, a1, a2, a3, b[1][0], b[1][1]);
                mma_f16(acc[i][3], a0, a1, a2, a3, b[1][2], b[1][3]);
            }
        }
        if (kt + 1 < nk) store_stage((kt + 1) & 1);
        __syncthreads();
    }

#pragma unroll
    for (int i = 0; i < 4; i++) {
#pragma unroll
        for (int j = 0; j < 4; j++) {
            int r0 = m0 + wm * 64 + i * 16 + grp;
            int r1 = r0 + 8;
            int c  = n0 + wn * 32 + j * 8 + qid * 2;
            *(float2*)(C + (size_t)r0 * ldbc + c) = make_float2(acc[i][j][0], acc[i][j][1]);
            *(float2*)(C + (size_t)r1 * ldbc + c) = make_float2(acc[i][j][2], acc[i][j][3]);
        }
    }
}

// ============ fused upgate: 512 thr, block 128x128, warp 32x32, dual B + SiLU ============
__global__ __launch_bounds__(512, 1)
void hgemm_upgate(const float* __restrict__ A, int lda,
                  const float* __restrict__ B1, const float* __restrict__ B2,
                  float* __restrict__ C,
                  const int* __restrict__ ridx,
                  const int* __restrict__ tilee, long long bstride)
{
    extern __shared__ char smc[];
    int* ridx_sm = (int*)smc;
    char* sA  = smc + 512;
    char* sB1 = smc + 512 + 2 * ATB;
    char* sB2 = smc + 512 + 2 * ATB + 2 * BTB;

    const int m0 = blockIdx.y * 128, n0 = blockIdx.x * 128;
    int e = tilee[blockIdx.y];
    if (e < 0) return;
    B1 += (size_t)e * bstride;
    B2 += (size_t)e * bstride;

    const int tid = threadIdx.x, lane = tid & 31, wid = tid >> 5;
    const int wm = wid & 3, wn = wid >> 2;
    const int grp = lane >> 2, qid = lane & 3;

    if (tid < 128) ridx_sm[tid] = ridx[m0 + tid];
    __syncthreads();

    const uint32_t sAu = smem_u32(sA), sB1u = smem_u32(sB1), sB2u = smem_u32(sB2);

    int ar[2], ak[2], bk[2], bn[2];
#pragma unroll
    for (int i = 0; i < 2; i++) {
        int idx = i * 512 + tid;
        ar[i] = idx >> 3; ak[i] = (idx & 7) << 2;
        bk[i] = idx >> 5; bn[i] = (idx & 31) << 2;
    }

    const int aRow = lane & 15, aKoff = (lane >> 4) << 3;
    const int lK = lane & 7, mv = lane >> 3;
    const int bKoff = (mv & 1) << 3, bNoff = (mv >> 1) << 3;

    float acc1[2][4][4] = {}, acc2[2][4][4] = {};
    float4 ra[2], rb1[2], rb2[2];
    const int nk = HID >> 5;

    auto load_stage = [&](int kt) {
        const int k0 = kt << 5;
#pragma unroll
        for (int i = 0; i < 2; i++) {
            int r = ridx_sm[ar[i]];
            ra[i] = (r >= 0) ? *(const float4*)(A + (size_t)r * lda + k0 + ak[i])
                             : make_float4(0.f, 0.f, 0.f, 0.f);
            rb1[i] = *(const float4*)(B1 + (size_t)(k0 + bk[i]) * FDIM + n0 + bn[i]);
            rb2[i] = *(const float4*)(B2 + (size_t)(k0 + bk[i]) * FDIM + n0 + bn[i]);
        }
    };
    auto store_stage = [&](int b) {
        char* Ab  = sA + b * ATB;
        char* B1b = sB1 + b * BTB;
        char* B2b = sB2 + b * BTB;
#pragma unroll
        for (int i = 0; i < 2; i++) {
            uint2 va = { pack_h2(ra[i].x, ra[i].y), pack_h2(ra[i].z, ra[i].w) };
            *(uint2*)(Ab + offA(ar[i], ak[i])) = va;
            uint2 v1 = { pack_h2(rb1[i].x, rb1[i].y), pack_h2(rb1[i].z, rb1[i].w) };
            *(uint2*)(B1b + offB(bk[i], bn[i])) = v1;
            uint2 v2 = { pack_h2(rb2[i].x, rb2[i].y), pack_h2(rb2[i].z, rb2[i].w) };
            *(uint2*)(B2b + offB(bk[i], bn[i])) = v2;
        }
    };

    load_stage(0);
    store_stage(0);
    __syncthreads();

    for (int kt = 0; kt < nk; kt++) {
        if (kt + 1 < nk) load_stage(kt + 1);

        const uint32_t aB  = sAu + (kt & 1) * ATB;
        const uint32_t b1B = sB1u + (kt & 1) * BTB;
        const uint32_t b2B = sB2u + (kt & 1) * BTB;
#pragma unroll
        for (int s = 0; s < 2; s++) {
            uint32_t u[2][4], g[2][4];
#pragma unroll
            for (int gg = 0; gg < 2; gg++) {
                int bo = offB(s * 16 + bKoff + lK, wn * 32 + gg * 16 + bNoff);
                ldsm_x4t(u[gg][0], u[gg][1], u[gg][2], u[gg][3], b1B + bo);
                ldsm_x4t(g[gg][0], g[gg][1], g[gg][2], g[gg][3], b2B + bo);
            }
#pragma unroll
            for (int i = 0; i < 2; i++) {
                uint32_t a0, a1, a2, a3;
                ldsm_x4(a0, a1, a2, a3,
                        aB + offA(wm * 32 + i * 16 + aRow, s * 16 + aKoff));
                mma_f16(acc1[i][0], a0, a1, a2, a3, u[0][0], u[0][1]);
                mma_f16(acc1[i][1], a0, a1, a2, a3, u[0][2], u[0][3]);
                mma_f16(acc1[i][2], a0, a1, a2, a3, u[1][0], u[1][1]);
                mma_f16(acc1[i][3], a0, a1, a2, a3, u[1][2], u[1][3]);
                mma_f16(acc2[i][0], a0, a1, a2, a3, g[0][0], g[0][1]);
                mma_f16(acc2[i][1], a0, a1, a2, a3, g[0][2], g[0][3]);
                mma_f16(acc2[i][2], a0, a1, a2, a3, g[1][0], g[1][1]);
                mma_f16(acc2[i][3], a0, a1, a2, a3, g[1][2], g[1][3]);
            }
        }

        if (kt + 1 < nk) store_stage((kt + 1) & 1);
        __syncthreads();
    }

#pragma unroll
    for (int i = 0; i < 2; i++) {
#pragma unroll
        for (int j = 0; j < 4; j++) {
            int r0 = m0 + wm * 32 + i * 16 + grp;
            int r1 = r0 + 8;
            int c  = n0 + wn * 32 + j * 8 + qid * 2;
            float uu, gg;
            float2 v0, v1;
            uu = acc1[i][j][0]; gg = acc2[i][j][0]; v0.x = (uu / (1.f + expf(-uu))) * gg;
            uu = acc1[i][j][1]; gg = acc2[i][j][1]; v0.y = (uu / (1.f + expf(-uu))) * gg;
            uu = acc1[i][j][2]; gg = acc2[i][j][2]; v1.x = (uu / (1.f + expf(-uu))) * gg;
            uu = acc1[i][j][3]; gg = acc2[i][j][3]; v1.y = (uu / (1.f + expf(-uu))) * gg;
            *(float2*)(C + (size_t)r0 * FDIM + c) = v0;
            *(float2*)(C + (size_t)r1 * FDIM + c) = v1;
        }
    }
}

// ============ tensor-core scores: P_h = fp16(SCALE * Q_h @ K_g^T) ============
// grid (8, 8, NH); causal skip above diagonal. Both operands [rows][HD] -> non-trans ldsm.
__global__ __launch_bounds__(256, 2)
void attn_scores_h()
{
    if (blockIdx.x > blockIdx.y) return;
    extern __shared__ char smc[];
    char* sA = smc + 512;
    char* sB = smc + 512 + 2 * ATB;

    const int h = blockIdx.z;
    const int m0 = blockIdx.y * 128, n0 = blockIdx.x * 128;
    const float* A = g_q + h * HD;           // lda = 2048
    const float* B = g_k + (h >> 2) * HD;    // ldb = 512
    __half* P = g_Ph + (size_t)h * SEQ * SEQ;

    const int tid = threadIdx.x, lane = tid & 31, wid = tid >> 5;
    const int wm = wid & 1, wn = wid >> 1;
    const int grp = lane >> 2, qid = lane & 3;

    const uint32_t sAu = smem_u32(sA), sBu = smem_u32(sB);

    int ar[4], ak[4];
#pragma unroll
    for (int i = 0; i < 4; i++) {
        int idx = i * 256 + tid;
        ar[i] = idx >> 3; ak[i] = (idx & 7) << 2;
    }
    const int aRow = lane & 15, aKoff = (lane >> 4) << 3;

    float acc[4][4][4] = {};
    float4 ra[4], rb[4];

    auto load_stage = [&](int kt) {
        const int k0 = kt << 5;
#pragma unroll
        for (int i = 0; i < 4; i++) {
            ra[i] = *(const float4*)(A + (size_t)(m0 + ar[i]) * (NH * HD) + k0 + ak[i]);
            rb[i] = *(const float4*)(B + (size_t)(n0 + ar[i]) * (KVH * HD) + k0 + ak[i]);
        }
    };
    auto store_stage = [&](int b) {
        char* Ab = sA + b * ATB;
        char* Bb = sB + b * ATB;
#pragma unroll
        for (int i = 0; i < 4; i++) {
            uint2 va = { pack_h2(ra[i].x, ra[i].y), pack_h2(ra[i].z, ra[i].w) };
            *(uint2*)(Ab + offA(ar[i], ak[i])) = va;
            uint2 vb = { pack_h2(rb[i].x, rb[i].y), pack_h2(rb[i].z, rb[i].w) };
            *(uint2*)(Bb + offA(ar[i], ak[i])) = vb;
        }
    };

    load_stage(0);
    store_stage(0);
    __syncthreads();

    const int nk = HD >> 5;   // 4
    for (int kt = 0; kt < nk; kt++) {
        if (kt + 1 < nk) load_stage(kt + 1);
        const uint32_t aB = sAu + (kt & 1) * ATB;
        const uint32_t bB = sBu + (kt & 1) * ATB;
#pragma unroll
        for (int s = 0; s < 2; s++) {
            uint32_t b[2][4];
#pragma unroll
            for (int g = 0; g < 2; g++)
                ldsm_x4(b[g][0], b[g][1], b[g][2], b[g][3],
                        bB + offA(wn * 32 + g * 16 + aRow, s * 16 + aKoff));
#pragma unroll
            for (int i = 0; i < 4; i++) {
                uint32_t a0, a1, a2, a3;
                ldsm_x4(a0, a1, a2, a3,
                        aB + offA(wm * 64 + i * 16 + aRow, s * 16 + aKoff));
                // non-trans B: n-low octet = (r0, r2), n-high octet = (r1, r3)
                mma_f16(acc[i][0], a0, a1, a2, a3, b[0][0], b[0][2]);
                mma_f16(acc[i][1], a0, a1, a2, a3, b[0][1], b[0][3]);
                mma_f16(acc[i][2], a0, a1, a2, a3, b[1][0], b[1][2]);
                mma_f16(acc[i][3], a0, a1, a2, a3, b[1][1], b[1][3]);
            }
        }
        if (kt + 1 < nk) store_stage((kt + 1) & 1);
        __syncthreads();
    }

#pragma unroll
    for (int i = 0; i < 4; i++) {
#pragma unroll
        for (int j = 0; j < 4; j++) {
            int r0 = m0 + wm * 64 + i * 16 + grp;
            int r1 = r0 + 8;
            int c  = n0 + wn * 32 + j * 8 + qid * 2;
            *(__half2*)(P + (size_t)r0 * SEQ + c) =
                __floats2half2_rn(acc[i][j][0] * SCALE, acc[i][j][1] * SCALE);
            *(__half2*)(P + (size_t)r1 * SEQ + c) =
                __floats2half2_rn(acc[i][j][2] * SCALE, acc[i][j][3] * SCALE);
        }
    }
}

// ============ softmax on fp16 P (causal; zero-fills upper) ============
__global__ void softmax_h()
{
    int t = blockIdx.x, h = blockIdx.y, tid = threadIdx.x;
    __half* row = g_Ph + ((size_t)h * SEQ + t) * SEQ;
    int n = t + 1;
    __shared__ float sm[256];
    float mx = -1e30f;
    for (int j = tid; j < n; j += 256) mx = fmaxf(mx, __half2float(row[j]));
    sm[tid] = mx; __syncthreads();
    for (int o = 128; o > 0; o >>= 1) {
        if (tid < o) sm[tid] = fmaxf(sm[tid], sm[tid + o]);
        __syncthreads();
    }
    float m = sm[0];
    __syncthreads();
    float sum = 0.f;
    for (int j = tid; j < n; j += 256) {
        float e = __expf(__half2float(row[j]) - m);
        row[j] = __float2half(e);
        sum += e;
    }
    sm[tid] = sum; __syncthreads();
    for (int o = 128; o > 0; o >>= 1) {
        if (tid < o) sm[tid] += sm[tid + o];
        __syncthreads();
    }
    float inv = 1.f / sm[0];
    for (int j = tid; j < SEQ; j += 256)
        row[j] = (j < n) ? __float2half(__half2float(row[j]) * inv) : __float2half(0.f);
}

// ============ tensor-core PV: attn_h = P_h @ V_g ============
// grid (1, 8, NH). A = fp16 P (direct), B = V fp32 -> half (trans ldsm), k-limited.
__global__ __launch_bounds__(256, 2)
void attn_pv_h()
{
    extern __shared__ char smc[];
    char* sA = smc + 512;
    char* sB = smc + 512 + 2 * ATB;

    const int h = blockIdx.z;
    const int m0 = blockIdx.y * 128;
    const __half* A = g_Ph + (size_t)h * SEQ * SEQ;   // lda = SEQ (halves)
    const float* B = g_v + (h >> 2) * HD;             // ldb = 512
    float* C = g_attn + h * HD;                       // ldc = 2048

    const int tid = threadIdx.x, lane = tid & 31, wid = tid >> 5;
    const int wm = wid & 1, wn = wid >> 1;
    const int grp = lane >> 2, qid = lane & 3;

    const uint32_t sAu = smem_u32(sA), sBu = smem_u32(sB);

    int ar[4], ak[4], bk[4], bn[4];
#pragma unroll
    for (int i = 0; i < 4; i++) {
        int idx = i * 256 + tid;
        ar[i] = idx >> 3; ak[i] = (idx & 7) << 2;   // ak in halves
        bk[i] = idx >> 5; bn[i] = (idx & 31) << 2;
    }
    const int aRow = lane & 15, aKoff = (lane >> 4) << 3;
    const int lK = lane & 7, mv = lane >> 3;
    const int bKoff = (mv & 1) << 3, bNoff = (mv >> 1) << 3;

    float acc[4][4][4] = {};
    uint2 raw[4];
    float4 rb[4];
    const int nk = (m0 + 128) >> 5;

    auto load_stage = [&](int kt) {
        const int k0 = kt << 5;
#pragma unroll
        for (int i = 0; i < 4; i++) {
            raw[i] = *(const uint2*)(A + (size_t)(m0 + ar[i]) * SEQ + k0 + ak[i]);
            rb[i] = *(const float4*)(B + (size_t)(k0 + bk[i]) * (KVH * HD) + bn[i]);
        }
    };
    auto store_stage = [&](int b) {
        char* Ab = sA + b * ATB;
        char* Bb = sB + b * BTB;
#pragma unroll
        for (int i = 0; i < 4; i++) {
            *(uint2*)(Ab + offA(ar[i], ak[i])) = raw[i];
            uint2 vb = { pack_h2(rb[i].x, rb[i].y), pack_h2(rb[i].z, rb[i].w) };
            *(uint2*)(Bb + offB(bk[i], bn[i])) = vb;
        }
    };

    load_stage(0);
    store_stage(0);
    __syncthreads();

    for (int kt = 0; kt < nk; kt++) {
        if (kt + 1 < nk) load_stage(kt + 1);
        const uint32_t aB = sAu + (kt & 1) * ATB;
        const uint32_t bB = sBu + (kt & 1) * BTB;
#pragma unroll
        for (int s = 0; s < 2; s++) {
            uint32_t b[2][4];
#pragma unroll
            for (int g = 0; g < 2; g++)
                ldsm_x4t(b[g][0], b[g][1], b[g][2], b[g][3],
                         bB + offB(s * 16 + bKoff + lK, wn * 32 + g * 16 + bNoff));
#pragma unroll
            for (int i = 0; i < 4; i++) {
                uint32_t a0, a1, a2, a3;
                ldsm_x4(a0, a1, a2, a3,
                        aB + offA(wm * 64 + i * 16 + aRow, s * 16 + aKoff));
                mma_f16(acc[i][0], a0, a1, a2, a3, b[0][0], b[0][1]);
                mma_f16(acc[i][1], a0, a1, a2, a3, b[0][2], b[0][3]);
                mma_f16(acc[i][2], a0, a1, a2, a3, b[1][0], b[1][1]);
                mma_f16(acc[i][3], a0, a1, a2, a3, b[1][2], b[1][3]);
            }
        }
        if (kt + 1 < nk) store_stage((kt + 1) & 1);
        __syncthreads();
    }

#pragma unroll
    for (int i = 0; i < 4; i++) {
#pragma unroll
        for (int j = 0; j < 4; j++) {
            int r0 = m0 + wm * 64 + i * 16 + grp;
            int r1 = r0 + 8;
            int c  = wn * 32 + j * 8 + qid * 2;
            *(float2*)(C + (size_t)r0 * HID + c) = make_float2(acc[i][j][0], acc[i][j][1]);
            *(float2*)(C + (size_t)r1 * HID + c) = make_float2(acc[i][j][2], acc[i][j][3]);
        }
    }
}

// ---------------- RMSNorm ----------------
__global__ void rmsnorm_kernel(const float* __restrict__ x, const float* __restrict__ w,
                               float* __restrict__ y)
{
    int t = blockIdx.x;
    const float* xr = x + (size_t)t * HID;
    float ss = 0.f;
    for (int j = threadIdx.x; j < HID; j += 256) { float v = xr[j]; ss += v * v; }
    __shared__ float sm[256];
    sm[threadIdx.x] = ss; __syncthreads();
    for (int o = 128; o > 0; o >>= 1) {
        if (threadIdx.x < o) sm[threadIdx.x] += sm[threadIdx.x + o];
        __syncthreads();
    }
    float inv = rsqrtf(sm[0] / (float)HID + EPSV);
    for (int j = threadIdx.x; j < HID; j += 256)
        y[(size_t)t * HID + j] = w[j] * (xr[j] * inv);
}

// ---------------- RoPE ----------------
__global__ void rope_kernel(const float* __restrict__ cosb, const float* __restrict__ sinb)
{
    int t = blockIdx.x, hh = blockIdx.y, d = threadIdx.x;
    float* p = (hh < NH) ? (g_q + (size_t)t * NH * HD + hh * HD)
                         : (g_k + (size_t)t * KVH * HD + (hh - NH) * HD);
    __shared__ float buf[HD];
    float x = p[d];
    buf[d] = x;
    __syncthreads();
    float rot = (d < HD / 2) ? -buf[d + HD / 2] : buf[d - HD / 2];
    p[d] = x * cosb[t * HD + d] + rot * sinb[t * HD + d];
}

// ---------------- routing ----------------
__global__ void route_kernel(const float* __restrict__ gw)
{
    int t = blockIdx.x, tid = threadIdx.x;
    float acc[8] = {};
    for (int hh = tid; hh < HID; hh += 256) {
        float xv = g_xn2[(size_t)t * HID + hh];
        const float* gr = gw + hh * 8;
        float4 a0 = *(const float4*)gr, a1 = *(const float4*)(gr + 4);
        acc[0] += xv * a0.x; acc[1] += xv * a0.y; acc[2] += xv * a0.z; acc[3] += xv * a0.w;
        acc[4] += xv * a1.x; acc[5] += xv * a1.y; acc[6] += xv * a1.z; acc[7] += xv * a1.w;
    }
#pragma unroll
    for (int o = 16; o > 0; o >>= 1)
#pragma unroll
        for (int e = 0; e < 8; e++)
            acc[e] += __shfl_down_sync(0xffffffffu, acc[e], o);
    __shared__ float sm[8][8];
    int w = tid >> 5, lane = tid & 31;
    if (lane == 0)
#pragma unroll
        for (int e = 0; e < 8; e++) sm[w][e] = acc[e];
    __syncthreads();
    if (tid == 0) {
        float l[8];
        for (int e = 0; e < 8; e++) {
            float s = 0.f;
            for (int ww = 0; ww < 8; ww++) s += sm[ww][e];
            l[e] = s;
        }
        int i0 = 0;
        for (int e = 1; e < 8; e++) if (l[e] > l[i0]) i0 = e;
        int i1 = -1;
        for (int e = 0; e < 8; e++) if (e != i0 && (i1 < 0 || l[e] > l[i1])) i1 = e;
        float p0 = 1.f, p1 = expf(l[i1] - l[i0]);
        float s = p0 + p1;
        g_topi[t * 2] = i0; g_topi[t * 2 + 1] = i1;
        g_topw[t * 2] = p0 / s; g_topw[t * 2 + 1] = p1 / s;
    }
}

// ---------------- grouping ----------------
__global__ void group_kernel()
{
    int tid = threadIdx.x;
    for (int i = tid; i < PADROWS; i += 256) g_assign[i] = -1;
    if (tid < MTILES) g_tilee[tid] = -1;
    __shared__ int cnt[NEXP], off[NEXP];
    if (tid < NEXP) cnt[tid] = 0;
    __syncthreads();
    for (int a = tid; a < SEQ * 2; a += 256) atomicAdd(&cnt[g_topi[a]], 1);
    __syncthreads();
    if (tid == 0) {
        int cur = 0;
        for (int e = 0; e < NEXP; e++) {
            off[e] = cur;
            int tiles = (cnt[e] + 127) >> 7;
            for (int tt = 0; tt < tiles; tt++) g_tilee[(cur >> 7) + tt] = e;
            cur += tiles * 128;
        }
    }
    __syncthreads();
    int w = tid >> 5, lane = tid & 31;
    if (w < NEXP) {
        int e = w, base = off[e], filled = 0;
        for (int a0 = 0; a0 < SEQ * 2; a0 += 32) {
            int a = a0 + lane;
            int ti = g_topi[a];
            bool match = (ti == e);
            unsigned msk = __ballot_sync(0xffffffffu, match);
            if (match) {
                int rank = __popc(msk & ((1u << lane) - 1u));
                int slot = base + filled + rank;
                g_assign[slot] = a >> 1;
                g_slot[a] = slot;
            }
            filled += __popc(msk);
        }
    }
}

// ---------------- combine ----------------
__global__ void combine_kernel(float* __restrict__ out)
{
    int t = blockIdx.x;
    int s0 = g_slot[t * 2], s1 = g_slot[t * 2 + 1];
    float w0 = g_topw[t * 2], w1 = g_topw[t * 2 + 1];
    for (int j = threadIdx.x; j < HID; j += 256) {
        size_t o = (size_t)t * HID + j;
        out[o] = g_x1[o] + w0 * g_Dout[(size_t)s0 * HID + j]
                         + w1 * g_Dout[(size_t)s1 * HID + j];
    }
}

// ---------------- launch ----------------
extern "C" void kernel_launch(void* const* d_in, const int* in_sizes, int n_in,
                              void* d_out, int out_size)
{
    const float* hidden = (const float*)d_in[0];
    const float* cosb   = (const float*)d_in[1];
    const float* sinb   = (const float*)d_in[2];
    const float* q_w    = (const float*)d_in[5];
    const float* k_w    = (const float*)d_in[6];
    const float* v_w    = (const float*)d_in[7];
    const float* o_w    = (const float*)d_in[8];
    const float* ln1    = (const float*)d_in[9];
    const float* ln2    = (const float*)d_in[10];
    const float* gate_w = (const float*)d_in[11];
    const float* up_w   = (const float*)d_in[12];
    const float* gp_w   = (const float*)d_in[13];
    const float* down_w = (const float*)d_in[14];
    float* out = (float*)d_out;

    cudaFuncSetAttribute(hgemm,         cudaFuncAttributeMaxDynamicSharedMemorySize, HG_SMEM);
    cudaFuncSetAttribute(hgemm_qkv,     cudaFuncAttributeMaxDynamicSharedMemorySize, HG_SMEM);
    cudaFuncSetAttribute(hgemm_upgate,  cudaFuncAttributeMaxDynamicSharedMemorySize, UPG_SMEM);
    cudaFuncSetAttribute(attn_scores_h, cudaFuncAttributeMaxDynamicSharedMemorySize, HG_SMEM);
    cudaFuncSetAttribute(attn_pv_h,     cudaFuncAttributeMaxDynamicSharedMemorySize, HG_SMEM);

    void *p_xn, *p_q, *p_attn, *p_x1, *p_xn2, *p_hup, *p_dout, *p_assign, *p_tilee;
    cudaGetSymbolAddress(&p_xn, g_xn);
    cudaGetSymbolAddress(&p_q, g_q);
    cudaGetSymbolAddress(&p_attn, g_attn);
    cudaGetSymbolAddress(&p_x1, g_x1);
    cudaGetSymbolAddress(&p_xn2, g_xn2);
    cudaGetSymbolAddress(&p_hup, g_Hup);
    cudaGetSymbolAddress(&p_dout, g_Dout);
    cudaGetSymbolAddress(&p_assign, g_assign);
    cudaGetSymbolAddress(&p_tilee, g_tilee);
    void *p_k, *p_v;
    cudaGetSymbolAddress(&p_k, g_k);
    cudaGetSymbolAddress(&p_v, g_v);

    float* xn   = (float*)p_xn;
    float* qb   = (float*)p_q;
    float* kb   = (float*)p_k;
    float* vb   = (float*)p_v;
    float* at   = (float*)p_attn;
    float* x1   = (float*)p_x1;
    float* xn2  = (float*)p_xn2;
    float* hup  = (float*)p_hup;
    float* dout = (float*)p_dout;
    int* assign = (int*)p_assign;
    int* tilee  = (int*)p_tilee;

    rmsnorm_kernel<<<SEQ, 256>>>(hidden, ln1, xn);
    hgemm_qkv<<<dim3(24, 8), 256, HG_SMEM>>>(xn, q_w, k_w, v_w, qb, kb, vb);
    rope_kernel<<<dim3(SEQ, NH + KVH), HD>>>(cosb, sinb);
    attn_scores_h<<<dim3(8, 8, NH), 256, HG_SMEM>>>();
    softmax_h<<<dim3(SEQ, NH), 256>>>();
    attn_pv_h<<<dim3(1, 8, NH), 256, HG_SMEM>>>();
    hgemm<<<dim3(16, 8), 256, HG_SMEM>>>(at, HID, o_w, HID, hidden,
                                         x1, HID, HID, nullptr, nullptr, 0);
    rmsnorm_kernel<<<SEQ, 256>>>(x1, ln2, xn2);
    route_kernel<<<SEQ, 256>>>(gate_w);
    group_kernel<<<1, 256>>>();
    hgemm_upgate<<<dim3(FDIM / 128, MTILES), 512, UPG_SMEM>>>(
        xn2, HID, up_w, gp_w, hup, assign, tilee, (long long)HID * FDIM);
    hgemm<<<dim3(16, MTILES), 256, HG_SMEM>>>(
        hup, FDIM, down_w, HID, nullptr, dout, HID, FDIM,
        nullptr, tilee, (long long)FDIM * HID);
    combine_kernel<<<SEQ, 256>>>(out);
}